// round 2
// baseline (speedup 1.0000x reference)
#include <cuda_runtime.h>
#include <cuda_bf16.h>
#include <math.h>

#define BB 4
#define SS 2048
#define DMM 1024
#define NTOK (BB*SS)          /* 8192 */

// ---------------- scratch (__device__ globals; no allocs) ----------------
__device__ float g_Wcat[256*DMM];                 // 1 MB
__device__ float g_bcat[256];
__device__ float g_proj[(size_t)NTOK*256];        // 8 MB
__device__ float g_q[NTOK*64];                    // 2 MB
__device__ float g_k[NTOK*64];
__device__ float g_v[NTOK*64];
__device__ float g_alpha[NTOK*64];
__device__ float g_MT[128*128*64];                // 4 MB  [(c*128+d)*64 + j]
__device__ float g_kv[(size_t)NTOK*4096];         // 128 MB
__device__ float g_bin[NTOK*128];                 // 4 MB
__device__ float g_A[(size_t)NTOK*16384];         // 512 MB (permuted layout)
__device__ float g_c[NTOK*128];                   // 4 MB
__device__ float g_R[(size_t)NTOK*4096];          // 128 MB

// ---------------- concat weights (Wq|Wk|Wv|Wa -> 256x1024) ----------------
__global__ void concat_w(const float* __restrict__ Wq, const float* __restrict__ bq,
                         const float* __restrict__ Wk, const float* __restrict__ bk,
                         const float* __restrict__ Wv, const float* __restrict__ bv,
                         const float* __restrict__ Wa, const float* __restrict__ ba) {
    int idx = blockIdx.x*blockDim.x + threadIdx.x;
    if (idx < 256*DMM) {
        int r = idx / DMM, cc = idx % DMM;
        float w;
        if (r < 64)       w = Wq[r*DMM + cc];
        else if (r < 128) w = Wk[(r-64)*DMM + cc];
        else if (r < 192) w = Wv[(r-128)*DMM + cc];
        else              w = Wa[(r-192)*DMM + cc];
        g_Wcat[idx] = w;
    }
    if (idx < 256) {
        g_bcat[idx] = (idx < 64) ? bq[idx] :
                      (idx < 128) ? bk[idx-64] :
                      (idx < 192) ? bv[idx-128] : ba[idx-192];
    }
}

// ---------------- M_j = W_down[:, j-block] @ W_up[j-block, :] ----------------
// One block per j. Output to g_MT transposed: g_MT[(c*128+d)*64 + j].
__global__ __launch_bounds__(256) void build_M(const float* __restrict__ Wd,
                                               const float* __restrict__ Wu) {
    int j = blockIdx.x;
    __shared__ float sd[128][33];   // Wd[c][v-panel]
    __shared__ float su[32][128];   // Wu[v][d]
    int tid = threadIdx.x;
    int c0 = tid >> 1;
    int dbase = (tid & 1) * 64;
    float acc[64];
    #pragma unroll
    for (int i = 0; i < 64; i++) acc[i] = 0.f;

    for (int vp = 0; vp < 2; vp++) {
        for (int l = tid; l < 128*32; l += 256) {
            int c = l >> 5, v = l & 31;
            sd[c][v] = Wd[(size_t)c*4096 + j*64 + vp*32 + v];
        }
        for (int l = tid; l < 32*128; l += 256) {
            int v = l >> 7, d = l & 127;
            su[v][d] = Wu[(size_t)(j*64 + vp*32 + v)*128 + d];
        }
        __syncthreads();
        #pragma unroll 8
        for (int v = 0; v < 32; v++) {
            float a = sd[c0][v];
            #pragma unroll
            for (int d = 0; d < 64; d++)
                acc[d] += a * su[v][dbase + d];
        }
        __syncthreads();
    }
    for (int d = 0; d < 64; d++)
        g_MT[(size_t)(c0*128 + dbase + d)*64 + j] = acc[d];
}

// ---------------- generic fp32 GEMM: C[M,N] = A[M,K] @ B[N,K]^T ----------------
// MODE 0: +bias plain store. MODE 1: plain store. MODE 2: permuted store for recurrence.
// M,N multiples of 64; K multiple of 16. Block = 64x64 tile, 256 threads.
template<int MODE>
__global__ void __launch_bounds__(256) gemm_nt(const float* __restrict__ A,
                                               const float* __restrict__ B,
                                               const float* __restrict__ bias,
                                               float* __restrict__ C,
                                               int M, int N, int K) {
    __shared__ float As[16][68];
    __shared__ float Bs[16][68];
    int tid = threadIdx.x;
    int tx = tid & 15, ty = tid >> 4;
    int row0 = blockIdx.y*64, col0 = blockIdx.x*64;
    int lr = tid >> 2, lc = (tid & 3) * 4;
    const float* Ap = A + (size_t)(row0+lr)*K + lc;
    const float* Bp = B + (size_t)(col0+lr)*K + lc;
    float acc[4][4] = {};
    for (int k0 = 0; k0 < K; k0 += 16) {
        float4 a4 = *(const float4*)(Ap + k0);
        float4 b4 = *(const float4*)(Bp + k0);
        As[lc+0][lr]=a4.x; As[lc+1][lr]=a4.y; As[lc+2][lr]=a4.z; As[lc+3][lr]=a4.w;
        Bs[lc+0][lr]=b4.x; Bs[lc+1][lr]=b4.y; Bs[lc+2][lr]=b4.z; Bs[lc+3][lr]=b4.w;
        __syncthreads();
        #pragma unroll
        for (int kk = 0; kk < 16; kk++) {
            float4 av = *(const float4*)&As[kk][ty*4];
            float4 bv = *(const float4*)&Bs[kk][tx*4];
            float a[4] = {av.x, av.y, av.z, av.w};
            float b[4] = {bv.x, bv.y, bv.z, bv.w};
            #pragma unroll
            for (int i = 0; i < 4; i++)
                #pragma unroll
                for (int jj = 0; jj < 4; jj++)
                    acc[i][jj] += a[i]*b[jj];
        }
        __syncthreads();
    }
    #pragma unroll
    for (int i = 0; i < 4; i++) {
        int r = row0 + ty*4 + i;
        float4 o;
        o.x = acc[i][0]; o.y = acc[i][1]; o.z = acc[i][2]; o.w = acc[i][3];
        if (MODE == 0) {
            const float* bp = bias + col0 + tx*4;
            o.x += bp[0]; o.y += bp[1]; o.z += bp[2]; o.w += bp[3];
        }
        if (MODE == 2) {
            // permuted store: n = c*128 + d; token row r.
            // float4 position = i_*512 + c*4 + qd, with i_ = (irot - 2*qd) & 7
            int n0 = col0 + tx*4;
            int cIdx = n0 >> 7;
            int d0 = n0 & 127;
            int qd = d0 >> 5;
            int irot = (d0 & 31) >> 2;
            int i_ = (irot - 2*qd) & 7;
            size_t pos = (size_t)i_*512 + cIdx*4 + qd;
            ((float4*)C)[(size_t)r*4096 + pos] = o;
        } else {
            *(float4*)(C + (size_t)r*N + col0 + tx*4) = o;
        }
    }
}

// ---------------- split proj -> q, k, v, sigmoid(alpha) ----------------
__global__ void split_proj() {
    int t = blockIdx.x;
    int tid = threadIdx.x;      // 256
    float val = g_proj[(size_t)t*256 + tid];
    int j = tid & 63;
    if (tid < 64)        g_q[t*64 + j] = val;
    else if (tid < 128)  g_k[t*64 + j] = val;
    else if (tid < 192)  g_v[t*64 + j] = val;
    else                 g_alpha[t*64 + j] = 1.f / (1.f + expf(-val));
}

// ---------------- kv outer product per token ----------------
__global__ void kv_outer() {
    int t = blockIdx.x;
    int tid = threadIdx.x;      // 256
    __shared__ float sk[64], sv[64];
    if (tid < 64)        sk[tid] = g_k[t*64 + tid];
    else if (tid < 128)  sv[tid-64] = g_v[t*64 + tid - 64];
    __syncthreads();
    float* dst = g_kv + (size_t)t*4096;
    #pragma unroll
    for (int i = 0; i < 16; i++) {
        int idx = tid + i*256;
        dst[idx] = sk[idx >> 6] * sv[idx & 63];
    }
}

// ---------------- serial recurrence: c_t = A_t c_{t-1} + b_t ----------------
// One block per batch, 512 threads. Thread (r = tid/4, qd = tid%4) covers
// row r, d in [qd*32, qd*32+32) in a rotated order matching the permuted A layout.
__global__ __launch_bounds__(512) void recurrence() {
    int b = blockIdx.x;
    int tid = threadIdx.x;
    int r = tid >> 2, qd = tid & 3;
    __shared__ float cs[2][128];
    if (tid < 128) { cs[0][tid] = 0.f; cs[1][tid] = 0.f; }
    __syncthreads();

    const float4* Abase = ((const float4*)g_A) + (size_t)b*SS*4096;
    float4 buf[8];
    #pragma unroll
    for (int i = 0; i < 8; i++) buf[i] = Abase[i*512 + tid];

    int p = 0;
    for (int t = 0; t < SS; t++) {
        float4 nbuf[8];
        if (t + 1 < SS) {
            const float4* An = Abase + (size_t)(t+1)*4096;
            #pragma unroll
            for (int i = 0; i < 8; i++) nbuf[i] = An[i*512 + tid];
        }
        float acc = 0.f;
        #pragma unroll
        for (int i = 0; i < 8; i++) {
            int idx4 = (qd << 3) + ((i + 2*qd) & 7);
            float4 cv = *(const float4*)(&cs[p][idx4 << 2]);
            acc += buf[i].x*cv.x + buf[i].y*cv.y + buf[i].z*cv.z + buf[i].w*cv.w;
        }
        acc += __shfl_xor_sync(0xffffffffu, acc, 1);
        acc += __shfl_xor_sync(0xffffffffu, acc, 2);
        if (qd == 0) {
            size_t tt = (size_t)b*SS + t;
            float cn = acc + g_bin[tt*128 + r];
            cs[p ^ 1][r] = cn;
            g_c[tt*128 + r] = cn;
        }
        __syncthreads();
        p ^= 1;
        #pragma unroll
        for (int i = 0; i < 8; i++) buf[i] = nbuf[i];
    }
}

// ---------------- readout: o[t,v] = sum_k q[t,k] * R[t, k*64+v] ----------------
__global__ __launch_bounds__(256) void readout(float* __restrict__ out) {
    int t = blockIdx.x*8 + (threadIdx.x >> 5);
    int l = threadIdx.x & 31;
    const float* Rr = g_R + (size_t)t*4096;
    const float* qr = g_q + t*64;
    float acc0 = 0.f, acc1 = 0.f;
    #pragma unroll 8
    for (int k = 0; k < 64; k++) {
        float qk = __ldg(qr + k);
        acc0 += qk * Rr[k*64 + l];
        acc1 += qk * Rr[k*64 + 32 + l];
    }
    out[t*64 + l]      = acc0;
    out[t*64 + 32 + l] = acc1;
}

// ---------------- host launcher ----------------
extern "C" void kernel_launch(void* const* d_in, const int* in_sizes, int n_in,
                              void* d_out, int out_size) {
    const float* x   = (const float*)d_in[0];
    const float* Wq  = (const float*)d_in[1];
    const float* bq  = (const float*)d_in[2];
    const float* Wk  = (const float*)d_in[3];
    const float* bk  = (const float*)d_in[4];
    const float* Wv  = (const float*)d_in[5];
    const float* bv  = (const float*)d_in[6];
    const float* Wa  = (const float*)d_in[7];
    const float* ba  = (const float*)d_in[8];
    const float* Wdn = (const float*)d_in[9];
    const float* Wup = (const float*)d_in[10];
    float* out = (float*)d_out;

    float *pProj, *pKv, *pBin, *pA, *pC, *pR, *pAlpha, *pMT, *pWcat, *pBcat;
    cudaGetSymbolAddress((void**)&pProj, g_proj);
    cudaGetSymbolAddress((void**)&pKv,   g_kv);
    cudaGetSymbolAddress((void**)&pBin,  g_bin);
    cudaGetSymbolAddress((void**)&pA,    g_A);
    cudaGetSymbolAddress((void**)&pC,    g_c);
    cudaGetSymbolAddress((void**)&pR,    g_R);
    cudaGetSymbolAddress((void**)&pAlpha,g_alpha);
    cudaGetSymbolAddress((void**)&pMT,   g_MT);
    cudaGetSymbolAddress((void**)&pWcat, g_Wcat);
    cudaGetSymbolAddress((void**)&pBcat, g_bcat);

    // 1. concat weights
    concat_w<<<1024, 256>>>(Wq, bq, Wk, bk, Wv, bv, Wa, ba);
    // 2. M matrices (transposed layout)
    build_M<<<64, 256>>>(Wdn, Wup);
    // 3. fused projection: proj = x @ Wcat^T + bcat   [8192 x 256]
    gemm_nt<0><<<dim3(4, 128), 256>>>(x, pWcat, pBcat, pProj, NTOK, 256, DMM);
    // 4. split + sigmoid
    split_proj<<<NTOK, 256>>>();
    // 5. per-token outer products
    kv_outer<<<NTOK, 256>>>();
    // 6. b_in = kv @ W_down^T   [8192 x 128]
    gemm_nt<1><<<dim3(2, 128), 256>>>(pKv, Wdn, nullptr, pBin, NTOK, 128, 4096);
    // 7. A = alpha @ MT^T  [8192 x 16384], permuted store
    gemm_nt<2><<<dim3(256, 128), 256>>>(pAlpha, pMT, nullptr, pA, NTOK, 16384, 64);
    // 8. serial recurrence
    recurrence<<<BB, 512>>>();
    // 9. R = c @ W_up^T   [8192 x 4096]
    gemm_nt<1><<<dim3(64, 128), 256>>>(pC, Wup, nullptr, pR, NTOK, 4096, 128);
    // 10. readout -> out
    readout<<<NTOK/8, 256>>>(out);
}

// round 3
// speedup vs baseline: 1.0381x; 1.0381x over previous
#include <cuda_runtime.h>
#include <cuda_bf16.h>
#include <math.h>

#define BB 4
#define SS 2048
#define DMM 1024
#define NTOK (BB*SS)          /* 8192 */

// ---------------- scratch (__device__ globals; no allocs) ----------------
__device__ float g_Wcat[256*DMM];                 // 1 MB
__device__ float g_bcat[256];
__device__ float g_proj[(size_t)NTOK*256];        // 8 MB
__device__ float g_q[NTOK*64];                    // 2 MB
__device__ float g_k[NTOK*64];
__device__ float g_v[NTOK*64];
__device__ float g_alpha[NTOK*64];
__device__ float g_MT[128*128*64];                // 4 MB  [(c*128+d)*64 + j]
__device__ float g_Wd2[8192*64];                  // 2 MB  [(c*64+v)][j]
__device__ float g_Wu3[8192*64];                  // 2 MB  [(v*128+c)][k]
__device__ float g_y[(size_t)NTOK*8192];          // 256 MB
__device__ float g_G[(size_t)NTOK*8192];          // 256 MB
__device__ float g_bin[NTOK*128];                 // 4 MB
__device__ float g_A[(size_t)NTOK*16384];         // 512 MB (permuted layout)
__device__ float g_c[NTOK*128];                   // 4 MB

// ---------------- f32x2 helpers ----------------
__device__ __forceinline__ unsigned long long dupf(float a) {
    unsigned long long r;
    asm("mov.b64 %0, {%1, %1};" : "=l"(r) : "f"(a));
    return r;
}
__device__ __forceinline__ void fma2(unsigned long long& c, unsigned long long a, unsigned long long b) {
    asm("fma.rn.f32x2 %0, %1, %2, %0;" : "+l"(c) : "l"(a), "l"(b));
}
__device__ __forceinline__ void unpk(unsigned long long v, float& lo, float& hi) {
    asm("mov.b64 {%0, %1}, %2;" : "=f"(lo), "=f"(hi) : "l"(v));
}

// ---------------- concat weights (Wq|Wk|Wv|Wa -> 256x1024) ----------------
__global__ void concat_w(const float* __restrict__ Wq, const float* __restrict__ bq,
                         const float* __restrict__ Wk, const float* __restrict__ bk,
                         const float* __restrict__ Wv, const float* __restrict__ bv,
                         const float* __restrict__ Wa, const float* __restrict__ ba) {
    int idx = blockIdx.x*blockDim.x + threadIdx.x;
    if (idx < 256*DMM) {
        int r = idx / DMM, cc = idx % DMM;
        float w;
        if (r < 64)       w = Wq[r*DMM + cc];
        else if (r < 128) w = Wk[(r-64)*DMM + cc];
        else if (r < 192) w = Wv[(r-128)*DMM + cc];
        else              w = Wa[(r-192)*DMM + cc];
        g_Wcat[idx] = w;
    }
    if (idx < 256) {
        g_bcat[idx] = (idx < 64) ? bq[idx] :
                      (idx < 128) ? bk[idx-64] :
                      (idx < 192) ? bv[idx-128] : ba[idx-192];
    }
}

// ---------------- weight transposes for reassociated bilinears ----------------
__global__ void make_wd2(const float* __restrict__ Wd) {
    int idx = blockIdx.x*256 + threadIdx.x;          // over 128*4096
    int c = idx >> 12, rest = idx & 4095;
    int j = rest >> 6, v = rest & 63;
    g_Wd2[(size_t)((c<<6) + v)*64 + j] = Wd[idx];
}
__global__ void make_wu3(const float* __restrict__ Wu) {
    int idx = blockIdx.x*256 + threadIdx.x;          // over 4096*128
    int kv = idx >> 7, c = idx & 127;
    int k = kv >> 6, v = kv & 63;
    g_Wu3[(size_t)(v*128 + c)*64 + k] = Wu[idx];
}

// ---------------- M_j = W_down[:, j-block] @ W_up[j-block, :] ----------------
__global__ __launch_bounds__(256) void build_M(const float* __restrict__ Wd,
                                               const float* __restrict__ Wu) {
    int j = blockIdx.x;
    __shared__ float sd[128][33];
    __shared__ float su[32][128];
    int tid = threadIdx.x;
    int c0 = tid >> 1;
    int dbase = (tid & 1) * 64;
    float acc[64];
    #pragma unroll
    for (int i = 0; i < 64; i++) acc[i] = 0.f;

    for (int vp = 0; vp < 2; vp++) {
        for (int l = tid; l < 128*32; l += 256) {
            int c = l >> 5, v = l & 31;
            sd[c][v] = Wd[(size_t)c*4096 + j*64 + vp*32 + v];
        }
        for (int l = tid; l < 32*128; l += 256) {
            int v = l >> 7, d = l & 127;
            su[v][d] = Wu[(size_t)(j*64 + vp*32 + v)*128 + d];
        }
        __syncthreads();
        #pragma unroll 8
        for (int v = 0; v < 32; v++) {
            float a = sd[c0][v];
            #pragma unroll
            for (int d = 0; d < 64; d++)
                acc[d] += a * su[v][dbase + d];
        }
        __syncthreads();
    }
    for (int d = 0; d < 64; d++)
        g_MT[(size_t)(c0*128 + dbase + d)*64 + j] = acc[d];
}

// ---------------- fp32 GEMM (f32x2): C[M,N] = A[M,K] @ B[N,K]^T ----------------
// 128x128 CTA tile, 256 threads, 8x8 microtile, K-tile 16, double-buffered.
// MODE 0: +bias. MODE 1: plain. MODE 2: permuted store for recurrence A-layout.
template<int MODE>
__global__ void __launch_bounds__(256) gemm2(const float* __restrict__ A,
                                             const float* __restrict__ B,
                                             const float* __restrict__ bias,
                                             float* __restrict__ C,
                                             int M, int N, int K) {
    __shared__ __align__(16) float As[2][16][132];
    __shared__ __align__(16) float Bs[2][16][132];
    int tid = threadIdx.x;
    int tx = tid & 15, ty = tid >> 4;
    int row0 = blockIdx.y*128, col0 = blockIdx.x*128;
    int lr = tid >> 1;              // 0..127
    int lk = (tid & 1) * 8;         // 0 or 8
    const float* Ap = A + (size_t)(row0+lr)*K + lk;
    const float* Bp = B + (size_t)(col0+lr)*K + lk;

    unsigned long long acc[8][4];
    #pragma unroll
    for (int i = 0; i < 8; i++)
        #pragma unroll
        for (int j = 0; j < 4; j++) acc[i][j] = 0ULL;

    int nt = K >> 4;

    // prologue: load tile 0 into buffer 0
    {
        float4 a0 = *(const float4*)(Ap + 0);
        float4 a1 = *(const float4*)(Ap + 4);
        float4 b0 = *(const float4*)(Bp + 0);
        float4 b1 = *(const float4*)(Bp + 4);
        As[0][lk+0][lr]=a0.x; As[0][lk+1][lr]=a0.y; As[0][lk+2][lr]=a0.z; As[0][lk+3][lr]=a0.w;
        As[0][lk+4][lr]=a1.x; As[0][lk+5][lr]=a1.y; As[0][lk+6][lr]=a1.z; As[0][lk+7][lr]=a1.w;
        Bs[0][lk+0][lr]=b0.x; Bs[0][lk+1][lr]=b0.y; Bs[0][lk+2][lr]=b0.z; Bs[0][lk+3][lr]=b0.w;
        Bs[0][lk+4][lr]=b1.x; Bs[0][lk+5][lr]=b1.y; Bs[0][lk+6][lr]=b1.z; Bs[0][lk+7][lr]=b1.w;
    }
    __syncthreads();

    #pragma unroll 1
    for (int t = 0; t < nt; t++) {
        int cur = t & 1;
        float4 a0, a1, b0, b1;
        if (t + 1 < nt) {
            int k0 = (t+1) << 4;
            a0 = *(const float4*)(Ap + k0);
            a1 = *(const float4*)(Ap + k0 + 4);
            b0 = *(const float4*)(Bp + k0);
            b1 = *(const float4*)(Bp + k0 + 4);
        }
        #pragma unroll
        for (int kk = 0; kk < 16; kk++) {
            float4 af0 = *(const float4*)&As[cur][kk][ty*8];
            float4 af1 = *(const float4*)&As[cur][kk][ty*8 + 4];
            ulonglong2 bv0 = *(const ulonglong2*)&Bs[cur][kk][tx*8];
            ulonglong2 bv1 = *(const ulonglong2*)&Bs[cur][kk][tx*8 + 4];
            float av[8] = {af0.x, af0.y, af0.z, af0.w, af1.x, af1.y, af1.z, af1.w};
            unsigned long long bw[4] = {bv0.x, bv0.y, bv1.x, bv1.y};
            #pragma unroll
            for (int i = 0; i < 8; i++) {
                unsigned long long ad = dupf(av[i]);
                #pragma unroll
                for (int j = 0; j < 4; j++) fma2(acc[i][j], ad, bw[j]);
            }
        }
        if (t + 1 < nt) {
            int nb = cur ^ 1;
            As[nb][lk+0][lr]=a0.x; As[nb][lk+1][lr]=a0.y; As[nb][lk+2][lr]=a0.z; As[nb][lk+3][lr]=a0.w;
            As[nb][lk+4][lr]=a1.x; As[nb][lk+5][lr]=a1.y; As[nb][lk+6][lr]=a1.z; As[nb][lk+7][lr]=a1.w;
            Bs[nb][lk+0][lr]=b0.x; Bs[nb][lk+1][lr]=b0.y; Bs[nb][lk+2][lr]=b0.z; Bs[nb][lk+3][lr]=b0.w;
            Bs[nb][lk+4][lr]=b1.x; Bs[nb][lk+5][lr]=b1.y; Bs[nb][lk+6][lr]=b1.z; Bs[nb][lk+7][lr]=b1.w;
        }
        __syncthreads();
    }

    // epilogue
    #pragma unroll
    for (int i = 0; i < 8; i++) {
        int m = row0 + ty*8 + i;
        float4 o0, o1;
        unpk(acc[i][0], o0.x, o0.y); unpk(acc[i][1], o0.z, o0.w);
        unpk(acc[i][2], o1.x, o1.y); unpk(acc[i][3], o1.z, o1.w);
        if (MODE == 0) {
            const float* bp = bias + col0 + tx*8;
            o0.x += bp[0]; o0.y += bp[1]; o0.z += bp[2]; o0.w += bp[3];
            o1.x += bp[4]; o1.y += bp[5]; o1.z += bp[6]; o1.w += bp[7];
        }
        if (MODE == 2) {
            #pragma unroll
            for (int jj = 0; jj < 2; jj++) {
                int n = col0 + tx*8 + jj*4;
                int cI = n >> 7, d0 = n & 127;
                int qd = d0 >> 5;
                int irot = (d0 & 31) >> 2;
                int i_ = (irot - 2*qd) & 7;
                ((float4*)C)[(size_t)m*4096 + i_*512 + cI*4 + qd] = jj ? o1 : o0;
            }
        } else {
            *(float4*)(C + (size_t)m*N + col0 + tx*8) = o0;
            *(float4*)(C + (size_t)m*N + col0 + tx*8 + 4) = o1;
        }
    }
}

// ---------------- split proj -> q, k, v, sigmoid(alpha) ----------------
__global__ void split_proj() {
    int t = blockIdx.x;
    int tid = threadIdx.x;      // 256
    float val = g_proj[(size_t)t*256 + tid];
    int j = tid & 63;
    if (tid < 64)        g_q[t*64 + j] = val;
    else if (tid < 128)  g_k[t*64 + j] = val;
    else if (tid < 192)  g_v[t*64 + j] = val;
    else                 g_alpha[t*64 + j] = 1.f / (1.f + expf(-val));
}

// ---------------- b_in[t,c] = sum_v y[t, c*64+v] * v_t[v] ----------------
__global__ __launch_bounds__(256) void bin_contract() {
    int t = blockIdx.x;
    int tid = threadIdx.x;
    __shared__ float sv[64];
    if (tid < 64) sv[tid] = g_v[t*64 + tid];
    __syncthreads();
    int c = tid >> 1, half = tid & 1;
    const float4* yp = (const float4*)(g_y + (size_t)t*8192 + c*64 + half*32);
    float acc = 0.f;
    #pragma unroll
    for (int i = 0; i < 8; i++) {
        float4 yv = yp[i];
        const float* vp = &sv[half*32 + i*4];
        acc += yv.x*vp[0] + yv.y*vp[1] + yv.z*vp[2] + yv.w*vp[3];
    }
    acc += __shfl_xor_sync(0xffffffffu, acc, 1);
    if (half == 0) g_bin[t*128 + c] = acc;
}

// ---------------- serial recurrence: c_t = A_t c_{t-1} + b_t ----------------
__global__ __launch_bounds__(512) void recurrence() {
    int b = blockIdx.x;
    int tid = threadIdx.x;
    int r = tid >> 2, qd = tid & 3;
    __shared__ float cs[2][128];
    if (tid < 128) { cs[0][tid] = 0.f; cs[1][tid] = 0.f; }
    __syncthreads();

    const float4* Abase = ((const float4*)g_A) + (size_t)b*SS*4096;
    float4 buf[8];
    #pragma unroll
    for (int i = 0; i < 8; i++) buf[i] = Abase[i*512 + tid];

    int p = 0;
    for (int t = 0; t < SS; t++) {
        float4 nbuf[8];
        if (t + 1 < SS) {
            const float4* An = Abase + (size_t)(t+1)*4096;
            #pragma unroll
            for (int i = 0; i < 8; i++) nbuf[i] = An[i*512 + tid];
        }
        float acc = 0.f;
        #pragma unroll
        for (int i = 0; i < 8; i++) {
            int idx4 = (qd << 3) + ((i + 2*qd) & 7);
            float4 cv = *(const float4*)(&cs[p][idx4 << 2]);
            acc += buf[i].x*cv.x + buf[i].y*cv.y + buf[i].z*cv.z + buf[i].w*cv.w;
        }
        acc += __shfl_xor_sync(0xffffffffu, acc, 1);
        acc += __shfl_xor_sync(0xffffffffu, acc, 2);
        if (qd == 0) {
            size_t tt = (size_t)b*SS + t;
            float cn = acc + g_bin[tt*128 + r];
            cs[p ^ 1][r] = cn;
            g_c[tt*128 + r] = cn;
        }
        __syncthreads();
        p ^= 1;
        #pragma unroll
        for (int i = 0; i < 8; i++) buf[i] = nbuf[i];
    }
}

// ---------------- o[t,v] = sum_c G[t, v*128+c] * c[t,c] ----------------
__global__ __launch_bounds__(256) void o_contract(float* __restrict__ out) {
    int t = blockIdx.x;
    int tid = threadIdx.x;
    __shared__ float sc[128];
    if (tid < 128) sc[tid] = g_c[t*128 + tid];
    __syncthreads();
    int v = tid >> 2, qc = tid & 3;
    const float4* gp = (const float4*)(g_G + (size_t)t*8192 + v*128 + qc*32);
    float acc = 0.f;
    #pragma unroll
    for (int i = 0; i < 8; i++) {
        float4 gv = gp[i];
        const float* cp = &sc[qc*32 + i*4];
        acc += gv.x*cp[0] + gv.y*cp[1] + gv.z*cp[2] + gv.w*cp[3];
    }
    acc += __shfl_xor_sync(0xffffffffu, acc, 1);
    acc += __shfl_xor_sync(0xffffffffu, acc, 2);
    if (qc == 0) out[t*64 + v] = acc;
}

// ---------------- host launcher ----------------
extern "C" void kernel_launch(void* const* d_in, const int* in_sizes, int n_in,
                              void* d_out, int out_size) {
    const float* x   = (const float*)d_in[0];
    const float* Wq  = (const float*)d_in[1];
    const float* bq  = (const float*)d_in[2];
    const float* Wk  = (const float*)d_in[3];
    const float* bk  = (const float*)d_in[4];
    const float* Wv  = (const float*)d_in[5];
    const float* bv  = (const float*)d_in[6];
    const float* Wa  = (const float*)d_in[7];
    const float* ba  = (const float*)d_in[8];
    const float* Wdn = (const float*)d_in[9];
    const float* Wup = (const float*)d_in[10];
    float* out = (float*)d_out;

    float *pProj, *pY, *pG, *pA, *pAlpha, *pMT, *pWcat, *pBcat, *pQ, *pK, *pWd2, *pWu3;
    cudaGetSymbolAddress((void**)&pProj, g_proj);
    cudaGetSymbolAddress((void**)&pY,    g_y);
    cudaGetSymbolAddress((void**)&pG,    g_G);
    cudaGetSymbolAddress((void**)&pA,    g_A);
    cudaGetSymbolAddress((void**)&pAlpha,g_alpha);
    cudaGetSymbolAddress((void**)&pMT,   g_MT);
    cudaGetSymbolAddress((void**)&pWcat, g_Wcat);
    cudaGetSymbolAddress((void**)&pBcat, g_bcat);
    cudaGetSymbolAddress((void**)&pQ,    g_q);
    cudaGetSymbolAddress((void**)&pK,    g_k);
    cudaGetSymbolAddress((void**)&pWd2,  g_Wd2);
    cudaGetSymbolAddress((void**)&pWu3,  g_Wu3);

    // 1. weight prep
    concat_w<<<1024, 256>>>(Wq, bq, Wk, bk, Wv, bv, Wa, ba);
    build_M<<<64, 256>>>(Wdn, Wup);
    make_wd2<<<2048, 256>>>(Wdn);
    make_wu3<<<2048, 256>>>(Wup);
    // 2. fused projection: proj = x @ Wcat^T + bcat   [8192 x 256]
    gemm2<0><<<dim3(2, 64), 256>>>(x, pWcat, pBcat, pProj, NTOK, 256, DMM);
    split_proj<<<NTOK, 256>>>();
    // 3. y = k @ Wd2^T   [8192 x 8192], K=64
    gemm2<1><<<dim3(64, 64), 256>>>(pK, pWd2, nullptr, pY, NTOK, 8192, 64);
    bin_contract<<<NTOK, 256>>>();
    // 4. A = alpha @ MT^T  [8192 x 16384], K=64, permuted store
    gemm2<2><<<dim3(128, 64), 256>>>(pAlpha, pMT, nullptr, pA, NTOK, 16384, 64);
    // 5. G = q @ Wu3^T   [8192 x 8192], K=64
    gemm2<1><<<dim3(64, 64), 256>>>(pQ, pWu3, nullptr, pG, NTOK, 8192, 64);
    // 6. serial recurrence
    recurrence<<<BB, 512>>>();
    // 7. readout contraction -> out
    o_contract<<<NTOK, 256>>>(out);
}

// round 4
// speedup vs baseline: 1.2839x; 1.2368x over previous
#include <cuda_runtime.h>
#include <cuda_bf16.h>
#include <math.h>

#define BB 4
#define SS 2048
#define DMM 1024
#define NTOK (BB*SS)          /* 8192 */
#define CHL 64                /* chunk length */
#define NCH (NTOK/CHL)        /* 128 chunks */

// ---------------- scratch (__device__ globals; no allocs) ----------------
__device__ float g_Wcat[256*DMM];                 // 1 MB
__device__ float g_bcat[256];
__device__ float g_q[NTOK*64];
__device__ float g_k[NTOK*64];
__device__ float g_v[NTOK*64];
__device__ float g_alpha[NTOK*64];
__device__ float g_MT[128*128*64];                // 4 MB  [(c*128+d)*64 + j]
__device__ float g_Wd2[8192*64];                  // 2 MB  [(c*64+v)][j]
__device__ float g_Wu3[8192*64];                  // 2 MB  [(v*128+c)][k]
__device__ float g_y[(size_t)NTOK*8192];          // 256 MB
__device__ float g_G[(size_t)NTOK*8192];          // 256 MB
__device__ float g_bin[NTOK*128];                 // 4 MB
__device__ float g_A[(size_t)NTOK*16384];         // 512 MB (plain [t][c*128+d])
__device__ float g_P[(size_t)NCH*16384];          // 8 MB  chunk propagators
__device__ float g_d[NCH*128];                    // chunk offsets
__device__ float g_cb[NCH*128];                   // chunk-start states
__device__ float g_c[NTOK*128];                   // 4 MB

// ---------------- f32x2 helpers ----------------
__device__ __forceinline__ unsigned long long dupf(float a) {
    unsigned long long r;
    asm("mov.b64 %0, {%1, %1};" : "=l"(r) : "f"(a));
    return r;
}
__device__ __forceinline__ void fma2(unsigned long long& c, unsigned long long a, unsigned long long b) {
    asm("fma.rn.f32x2 %0, %1, %2, %0;" : "+l"(c) : "l"(a), "l"(b));
}
__device__ __forceinline__ void unpk(unsigned long long v, float& lo, float& hi) {
    asm("mov.b64 {%0, %1}, %2;" : "=f"(lo), "=f"(hi) : "l"(v));
}

// ---------------- merged prep: build_M | concat | wd2 | wu3 ----------------
__global__ __launch_bounds__(256) void prep_all(
        const float* __restrict__ Wq, const float* __restrict__ bq,
        const float* __restrict__ Wk, const float* __restrict__ bk,
        const float* __restrict__ Wv, const float* __restrict__ bv,
        const float* __restrict__ Wa, const float* __restrict__ ba,
        const float* __restrict__ Wd, const float* __restrict__ Wu) {
    __shared__ float sd[128][33];
    __shared__ float su[32][128];
    int bid = blockIdx.x;
    int tid = threadIdx.x;
    if (bid < 64) {
        // ---- build_M for j = bid ----
        int j = bid;
        int c0 = tid >> 1;
        int dbase = (tid & 1) * 64;
        float acc[64];
        #pragma unroll
        for (int i = 0; i < 64; i++) acc[i] = 0.f;
        for (int vp = 0; vp < 2; vp++) {
            for (int l = tid; l < 128*32; l += 256) {
                int c = l >> 5, v = l & 31;
                sd[c][v] = Wd[(size_t)c*4096 + j*64 + vp*32 + v];
            }
            for (int l = tid; l < 32*128; l += 256) {
                int v = l >> 7, d = l & 127;
                su[v][d] = Wu[(size_t)(j*64 + vp*32 + v)*128 + d];
            }
            __syncthreads();
            #pragma unroll 8
            for (int v = 0; v < 32; v++) {
                float a = sd[c0][v];
                #pragma unroll
                for (int d = 0; d < 64; d++)
                    acc[d] += a * su[v][dbase + d];
            }
            __syncthreads();
        }
        for (int d = 0; d < 64; d++)
            g_MT[(size_t)(c0*128 + dbase + d)*64 + j] = acc[d];
    } else if (bid < 1088) {
        // ---- concat weights ----
        int idx = (bid - 64)*256 + tid;
        int r = idx >> 10, cc = idx & 1023;
        float w;
        if (r < 64)       w = Wq[r*DMM + cc];
        else if (r < 128) w = Wk[(r-64)*DMM + cc];
        else if (r < 192) w = Wv[(r-128)*DMM + cc];
        else              w = Wa[(r-192)*DMM + cc];
        g_Wcat[idx] = w;
        if (bid == 64) {
            g_bcat[tid] = (tid < 64) ? bq[tid] :
                          (tid < 128) ? bk[tid-64] :
                          (tid < 192) ? bv[tid-128] : ba[tid-192];
        }
    } else if (bid < 3136) {
        // ---- wd2: g_Wd2[(c*64+v)*64 + j] = Wd[c][j*64+v] ----
        int idx = (bid - 1088)*256 + tid;       // over 128*4096
        int c = idx >> 12, rest = idx & 4095;
        int j = rest >> 6, v = rest & 63;
        g_Wd2[(size_t)((c<<6) + v)*64 + j] = Wd[idx];
    } else {
        // ---- wu3: g_Wu3[(v*128+c)*64 + k] = Wu[(k*64+v)*128 + c] ----
        int idx = (bid - 3136)*256 + tid;       // over 4096*128
        int kv = idx >> 7, c = idx & 127;
        int k = kv >> 6, v = kv & 63;
        g_Wu3[(size_t)(v*128 + c)*64 + k] = Wu[idx];
    }
}

// ---------------- fp32 GEMM (f32x2): C[M,N] = A[M,K] @ B[N,K]^T ----------------
// MODE 1: plain store. MODE 3: projection epilogue -> split q/k/v/sigmoid(alpha).
template<int MODE>
__global__ void __launch_bounds__(256) gemm2(const float* __restrict__ A,
                                             const float* __restrict__ B,
                                             float* __restrict__ C,
                                             int M, int N, int K) {
    __shared__ __align__(16) float As[2][16][132];
    __shared__ __align__(16) float Bs[2][16][132];
    int tid = threadIdx.x;
    int tx = tid & 15, ty = tid >> 4;
    int row0 = blockIdx.y*128, col0 = blockIdx.x*128;
    int lr = tid >> 1;              // 0..127
    int lk = (tid & 1) * 8;         // 0 or 8
    const float* Ap = A + (size_t)(row0+lr)*K + lk;
    const float* Bp = B + (size_t)(col0+lr)*K + lk;

    unsigned long long acc[8][4];
    #pragma unroll
    for (int i = 0; i < 8; i++)
        #pragma unroll
        for (int j = 0; j < 4; j++) acc[i][j] = 0ULL;

    int nt = K >> 4;
    {
        float4 a0 = *(const float4*)(Ap + 0);
        float4 a1 = *(const float4*)(Ap + 4);
        float4 b0 = *(const float4*)(Bp + 0);
        float4 b1 = *(const float4*)(Bp + 4);
        As[0][lk+0][lr]=a0.x; As[0][lk+1][lr]=a0.y; As[0][lk+2][lr]=a0.z; As[0][lk+3][lr]=a0.w;
        As[0][lk+4][lr]=a1.x; As[0][lk+5][lr]=a1.y; As[0][lk+6][lr]=a1.z; As[0][lk+7][lr]=a1.w;
        Bs[0][lk+0][lr]=b0.x; Bs[0][lk+1][lr]=b0.y; Bs[0][lk+2][lr]=b0.z; Bs[0][lk+3][lr]=b0.w;
        Bs[0][lk+4][lr]=b1.x; Bs[0][lk+5][lr]=b1.y; Bs[0][lk+6][lr]=b1.z; Bs[0][lk+7][lr]=b1.w;
    }
    __syncthreads();

    #pragma unroll 1
    for (int t = 0; t < nt; t++) {
        int cur = t & 1;
        float4 a0, a1, b0, b1;
        if (t + 1 < nt) {
            int k0 = (t+1) << 4;
            a0 = *(const float4*)(Ap + k0);
            a1 = *(const float4*)(Ap + k0 + 4);
            b0 = *(const float4*)(Bp + k0);
            b1 = *(const float4*)(Bp + k0 + 4);
        }
        #pragma unroll
        for (int kk = 0; kk < 16; kk++) {
            float4 af0 = *(const float4*)&As[cur][kk][ty*8];
            float4 af1 = *(const float4*)&As[cur][kk][ty*8 + 4];
            ulonglong2 bv0 = *(const ulonglong2*)&Bs[cur][kk][tx*8];
            ulonglong2 bv1 = *(const ulonglong2*)&Bs[cur][kk][tx*8 + 4];
            float av[8] = {af0.x, af0.y, af0.z, af0.w, af1.x, af1.y, af1.z, af1.w};
            unsigned long long bw[4] = {bv0.x, bv0.y, bv1.x, bv1.y};
            #pragma unroll
            for (int i = 0; i < 8; i++) {
                unsigned long long ad = dupf(av[i]);
                #pragma unroll
                for (int j = 0; j < 4; j++) fma2(acc[i][j], ad, bw[j]);
            }
        }
        if (t + 1 < nt) {
            int nb = cur ^ 1;
            As[nb][lk+0][lr]=a0.x; As[nb][lk+1][lr]=a0.y; As[nb][lk+2][lr]=a0.z; As[nb][lk+3][lr]=a0.w;
            As[nb][lk+4][lr]=a1.x; As[nb][lk+5][lr]=a1.y; As[nb][lk+6][lr]=a1.z; As[nb][lk+7][lr]=a1.w;
            Bs[nb][lk+0][lr]=b0.x; Bs[nb][lk+1][lr]=b0.y; Bs[nb][lk+2][lr]=b0.z; Bs[nb][lk+3][lr]=b0.w;
            Bs[nb][lk+4][lr]=b1.x; Bs[nb][lk+5][lr]=b1.y; Bs[nb][lk+6][lr]=b1.z; Bs[nb][lk+7][lr]=b1.w;
        }
        __syncthreads();
    }

    #pragma unroll
    for (int i = 0; i < 8; i++) {
        int m = row0 + ty*8 + i;
        float4 o0, o1;
        unpk(acc[i][0], o0.x, o0.y); unpk(acc[i][1], o0.z, o0.w);
        unpk(acc[i][2], o1.x, o1.y); unpk(acc[i][3], o1.z, o1.w);
        if (MODE == 3) {
            // add bias, then split to q/k/v/sigmoid(alpha). N=256.
            int n0 = col0 + tx*8;
            const float* bp = g_bcat + n0;
            o0.x += bp[0]; o0.y += bp[1]; o0.z += bp[2]; o0.w += bp[3];
            o1.x += bp[4]; o1.y += bp[5]; o1.z += bp[6]; o1.w += bp[7];
            int blk = n0 >> 6;                   // same for both float4s
            int w = n0 & 63;
            float* base = (blk == 0) ? g_q : (blk == 1) ? g_k : (blk == 2) ? g_v : g_alpha;
            if (blk == 3) {
                o0.x = 1.f/(1.f+expf(-o0.x)); o0.y = 1.f/(1.f+expf(-o0.y));
                o0.z = 1.f/(1.f+expf(-o0.z)); o0.w = 1.f/(1.f+expf(-o0.w));
                o1.x = 1.f/(1.f+expf(-o1.x)); o1.y = 1.f/(1.f+expf(-o1.y));
                o1.z = 1.f/(1.f+expf(-o1.z)); o1.w = 1.f/(1.f+expf(-o1.w));
            }
            *(float4*)(base + (size_t)m*64 + w)     = o0;
            *(float4*)(base + (size_t)m*64 + w + 4) = o1;
        } else {
            *(float4*)(C + (size_t)m*N + col0 + tx*8) = o0;
            *(float4*)(C + (size_t)m*N + col0 + tx*8 + 4) = o1;
        }
    }
}

// ---------------- b_in[t,c] = sum_v y[t, c*64+v] * v_t[v] ----------------
__global__ __launch_bounds__(256) void bin_contract() {
    int t = blockIdx.x;
    int tid = threadIdx.x;
    __shared__ float sv[64];
    if (tid < 64) sv[tid] = g_v[t*64 + tid];
    __syncthreads();
    int c = tid >> 1, half = tid & 1;
    const float4* yp = (const float4*)(g_y + (size_t)t*8192 + c*64 + half*32);
    float acc = 0.f;
    #pragma unroll
    for (int i = 0; i < 8; i++) {
        int ii = (i + 4*half) & 7;               // bank de-conflict rotation
        float4 yv = yp[ii];
        const float* vp = &sv[half*32 + ii*4];
        acc += yv.x*vp[0] + yv.y*vp[1] + yv.z*vp[2] + yv.w*vp[3];
    }
    acc += __shfl_xor_sync(0xffffffffu, acc, 1);
    if (half == 0) g_bin[t*128 + c] = acc;
}

// ---------------- pass A: per-chunk propagator P and offset d ----------------
// P <- A_t @ P (init I), d <- A_t d + b_t (init 0). 512 threads, 1 CTA/chunk.
__global__ __launch_bounds__(512) void passA_kern() {
    extern __shared__ float sm[];
    float* At = sm;                        // [128][132] transposed: At[k*132+r]=A[r][k]
    float* Ps = sm + 128*132;              // [2][128][132] row-major
    float* ds = sm + 3*128*132;            // [2][128]
    int tid = threadIdx.x;
    int chunk = blockIdx.x;
    int b = chunk >> 5, ci = chunk & 31;
    size_t tokBase = (size_t)b*SS + (size_t)ci*CHL;

    for (int idx = tid; idx < 128*132; idx += 512) {
        int r = idx/132, cc = idx - r*132;
        Ps[idx] = (r == cc) ? 1.f : 0.f;
        Ps[128*132 + idx] = 0.f;
    }
    if (tid < 128) { ds[tid] = 0.f; ds[128+tid] = 0.f; }

    int lr = tid >> 2;                     // row for A staging
    int kq = (tid & 3) * 32;               // k-quarter
    float4 rA[8];
    {
        const float4* A0 = (const float4*)(g_A + tokBase*16384);
        #pragma unroll
        for (int i = 0; i < 8; i++) rA[i] = A0[lr*32 + (tid&3)*8 + i];
    }
    __syncthreads();

    int tx = tid & 31, ty = tid >> 5;      // matmul: cols tx*4, rows ty*8
    int r2 = tid >> 2, q2 = tid & 3;       // d-update mapping
    int cur = 0;
    for (int s = 0; s < CHL; s++) {
        // stage A_t transposed
        #pragma unroll
        for (int i = 0; i < 8; i++) {
            float4 v = rA[i];
            int k0 = kq + i*4;
            At[(k0+0)*132 + lr] = v.x;
            At[(k0+1)*132 + lr] = v.y;
            At[(k0+2)*132 + lr] = v.z;
            At[(k0+3)*132 + lr] = v.w;
        }
        __syncthreads();
        // prefetch next A_t (latency hidden by matmul)
        if (s + 1 < CHL) {
            const float4* An = (const float4*)(g_A + (tokBase + s + 1)*16384);
            #pragma unroll
            for (int i = 0; i < 8; i++) rA[i] = An[lr*32 + (tid&3)*8 + i];
        }
        // matmul newP[r][n] = sum_k A[r][k] P[k][n]; fold d-update in
        unsigned long long acc[8][2];
        #pragma unroll
        for (int i = 0; i < 8; i++) { acc[i][0] = 0ULL; acc[i][1] = 0ULL; }
        float dacc = 0.f;
        const float* Pc = Ps + cur*128*132;
        const float* dc = ds + cur*128;
        #pragma unroll 4
        for (int k = 0; k < 128; k++) {
            float4 a0 = *(const float4*)&At[k*132 + ty*8];
            float4 a1 = *(const float4*)&At[k*132 + ty*8 + 4];
            ulonglong2 bb = *(const ulonglong2*)&Pc[k*132 + tx*4];
            float av[8] = {a0.x, a0.y, a0.z, a0.w, a1.x, a1.y, a1.z, a1.w};
            #pragma unroll
            for (int i = 0; i < 8; i++) {
                unsigned long long ad = dupf(av[i]);
                fma2(acc[i][0], ad, bb.x);
                fma2(acc[i][1], ad, bb.y);
            }
            if ((k >> 5) == q2) dacc += At[k*132 + r2] * dc[k];
        }
        dacc += __shfl_xor_sync(0xffffffffu, dacc, 1);
        dacc += __shfl_xor_sync(0xffffffffu, dacc, 2);
        float* Pn = Ps + (cur^1)*128*132;
        #pragma unroll
        for (int i = 0; i < 8; i++) {
            float4 o;
            unpk(acc[i][0], o.x, o.y); unpk(acc[i][1], o.z, o.w);
            *(float4*)&Pn[(ty*8 + i)*132 + tx*4] = o;
        }
        if (q2 == 0)
            ds[(cur^1)*128 + r2] = dacc + g_bin[(tokBase + s)*128 + r2];
        __syncthreads();
        cur ^= 1;
    }
    // write out P, d
    const float* Pf = Ps + cur*128*132;
    for (int idx = tid; idx < 16384; idx += 512) {
        int r = idx >> 7, cc = idx & 127;
        g_P[(size_t)chunk*16384 + idx] = Pf[r*132 + cc];
    }
    if (tid < 128) g_d[chunk*128 + tid] = ds[cur*128 + tid];
}

// ---------------- pass B: cross-chunk scan (per batch) ----------------
__global__ __launch_bounds__(512) void passB_kern() {
    int b = blockIdx.x;
    int tid = threadIdx.x;
    int r = tid >> 2, dq = tid & 3;
    __shared__ float cv[128], nv[128];
    if (tid < 128) cv[tid] = 0.f;
    __syncthreads();
    for (int i = 0; i < SS/CHL; i++) {
        int chunk = b*(SS/CHL) + i;
        if (tid < 128) g_cb[chunk*128 + tid] = cv[tid];
        __syncthreads();
        const float4* Pr = (const float4*)(g_P + (size_t)chunk*16384);
        float acc = 0.f;
        #pragma unroll
        for (int j = 0; j < 8; j++) {
            int jj = (j + 2*dq) & 7;
            float4 pv = Pr[tid*8 + jj];
            float4 c4 = *(const float4*)&cv[dq*32 + jj*4];
            acc += pv.x*c4.x + pv.y*c4.y + pv.z*c4.z + pv.w*c4.w;
        }
        acc += __shfl_xor_sync(0xffffffffu, acc, 1);
        acc += __shfl_xor_sync(0xffffffffu, acc, 2);
        if (dq == 0) nv[r] = acc + g_d[chunk*128 + r];
        __syncthreads();
        if (tid < 128) cv[tid] = nv[tid];
        __syncthreads();
    }
}

// ---------------- pass C: within-chunk recurrence, all chunks parallel ----------------
__global__ __launch_bounds__(512) void passC_kern() {
    int chunk = blockIdx.x;
    int b = chunk >> 5, ci = chunk & 31;
    size_t tokBase = (size_t)b*SS + (size_t)ci*CHL;
    int tid = threadIdx.x;
    int r = tid >> 2, dq = tid & 3;
    __shared__ float cs[2][128];
    if (tid < 128) cs[0][tid] = g_cb[chunk*128 + tid];
    __syncthreads();

    const float4* Ab = (const float4*)(g_A + tokBase*16384);
    float4 buf[8];
    #pragma unroll
    for (int i = 0; i < 8; i++) buf[i] = Ab[tid*8 + ((i + 2*dq) & 7)];

    int p = 0;
    for (int s = 0; s < CHL; s++) {
        float4 nbuf[8];
        if (s + 1 < CHL) {
            const float4* An = Ab + (size_t)(s+1)*4096;
            #pragma unroll
            for (int i = 0; i < 8; i++) nbuf[i] = An[tid*8 + ((i + 2*dq) & 7)];
        }
        float acc = 0.f;
        #pragma unroll
        for (int i = 0; i < 8; i++) {
            int ii = (i + 2*dq) & 7;
            float4 cv = *(const float4*)&cs[p][dq*32 + ii*4];
            acc += buf[i].x*cv.x + buf[i].y*cv.y + buf[i].z*cv.z + buf[i].w*cv.w;
        }
        acc += __shfl_xor_sync(0xffffffffu, acc, 1);
        acc += __shfl_xor_sync(0xffffffffu, acc, 2);
        if (dq == 0) {
            float cn = acc + g_bin[(tokBase + s)*128 + r];
            cs[p ^ 1][r] = cn;
            g_c[(tokBase + s)*128 + r] = cn;
        }
        __syncthreads();
        p ^= 1;
        #pragma unroll
        for (int i = 0; i < 8; i++) buf[i] = nbuf[i];
    }
}

// ---------------- o[t,v] = sum_c G[t, v*128+c] * c[t,c] ----------------
__global__ __launch_bounds__(256) void o_contract(float* __restrict__ out) {
    int t = blockIdx.x;
    int tid = threadIdx.x;
    __shared__ float sc[128];
    if (tid < 128) sc[tid] = g_c[t*128 + tid];
    __syncthreads();
    int v = tid >> 2, qc = tid & 3;
    const float4* gp = (const float4*)(g_G + (size_t)t*8192 + v*128 + qc*32);
    float acc = 0.f;
    #pragma unroll
    for (int i = 0; i < 8; i++) {
        int ii = (i + 2*qc) & 7;
        float4 gv = gp[ii];
        const float* cp = &sc[qc*32 + ii*4];
        acc += gv.x*cp[0] + gv.y*cp[1] + gv.z*cp[2] + gv.w*cp[3];
    }
    acc += __shfl_xor_sync(0xffffffffu, acc, 1);
    acc += __shfl_xor_sync(0xffffffffu, acc, 2);
    if (qc == 0) out[t*64 + v] = acc;
}

// ---------------- host launcher ----------------
extern "C" void kernel_launch(void* const* d_in, const int* in_sizes, int n_in,
                              void* d_out, int out_size) {
    const float* x   = (const float*)d_in[0];
    const float* Wq  = (const float*)d_in[1];
    const float* bq  = (const float*)d_in[2];
    const float* Wk  = (const float*)d_in[3];
    const float* bk  = (const float*)d_in[4];
    const float* Wv  = (const float*)d_in[5];
    const float* bv  = (const float*)d_in[6];
    const float* Wa  = (const float*)d_in[7];
    const float* ba  = (const float*)d_in[8];
    const float* Wdn = (const float*)d_in[9];
    const float* Wup = (const float*)d_in[10];
    float* out = (float*)d_out;

    float *pY, *pG, *pA, *pAlpha, *pMT, *pWcat, *pQ, *pK, *pWd2, *pWu3;
    cudaGetSymbolAddress((void**)&pY,    g_y);
    cudaGetSymbolAddress((void**)&pG,    g_G);
    cudaGetSymbolAddress((void**)&pA,    g_A);
    cudaGetSymbolAddress((void**)&pAlpha,g_alpha);
    cudaGetSymbolAddress((void**)&pMT,   g_MT);
    cudaGetSymbolAddress((void**)&pWcat, g_Wcat);
    cudaGetSymbolAddress((void**)&pQ,    g_q);
    cudaGetSymbolAddress((void**)&pK,    g_k);
    cudaGetSymbolAddress((void**)&pWd2,  g_Wd2);
    cudaGetSymbolAddress((void**)&pWu3,  g_Wu3);

    static const int PASSA_SMEM = (128*132 + 2*128*132 + 2*128) * 4;
    cudaFuncSetAttribute(passA_kern, cudaFuncAttributeMaxDynamicSharedMemorySize, PASSA_SMEM);

    // 1. merged weight prep
    prep_all<<<5184, 256>>>(Wq, bq, Wk, bk, Wv, bv, Wa, ba, Wdn, Wup);
    // 2. fused projection + split + sigmoid
    gemm2<3><<<dim3(2, 64), 256>>>(x, pWcat, nullptr, NTOK, 256, DMM);
    // 3. y = k @ Wd2^T   [8192 x 8192], K=64
    gemm2<1><<<dim3(64, 64), 256>>>(pK, pWd2, pY, NTOK, 8192, 64);
    // 4. A = alpha @ MT^T  [8192 x 16384], K=64, plain store   <-- ncu capture slot
    gemm2<1><<<dim3(128, 64), 256>>>(pAlpha, pMT, pA, NTOK, 16384, 64);
    // 5. b_in contraction
    bin_contract<<<NTOK, 256>>>();
    // 6. chunk propagators + offsets
    passA_kern<<<NCH, 512, PASSA_SMEM>>>();
    // 7. cross-chunk scan
    passB_kern<<<BB, 512>>>();
    // 8. G = q @ Wu3^T   [8192 x 8192], K=64
    gemm2<1><<<dim3(64, 64), 256>>>(pQ, pWu3, pG, NTOK, 8192, 64);
    // 9. within-chunk recurrence (parallel)
    passC_kern<<<NCH, 512>>>();
    // 10. readout contraction -> out
    o_contract<<<NTOK, 256>>>(out);
}

// round 6
// speedup vs baseline: 1.3476x; 1.0496x over previous
#include <cuda_runtime.h>
#include <cuda_bf16.h>
#include <math.h>

// R5 retry — container infra failure last round; source audited, unchanged logic.

#define BB 4
#define SS 2048
#define DMM 1024
#define NTOK (BB*SS)          /* 8192 */
#define CHL 64                /* chunk length */
#define NCH (NTOK/CHL)        /* 128 chunks */

// ---------------- scratch (__device__ globals; no allocs) ----------------
__device__ float g_Wcat[256*DMM];                 // 1 MB
__device__ float g_bcat[256];
__device__ float g_q[NTOK*64];
__device__ float g_k[NTOK*64];
__device__ float g_v[NTOK*64];
__device__ float g_alpha[NTOK*64];
__device__ float g_MT[128*128*64];                // 4 MB  [(c*128+d)*64 + j]
__device__ float g_Wd2[8192*64];                  // 2 MB  [(c*64+v)][j]
__device__ float g_Wu3[8192*64];                  // 2 MB  [(v*128+c)][k]
__device__ float g_bin[NTOK*128];                 // 4 MB
__device__ float g_A[(size_t)NTOK*16384];         // 512 MB (plain [t][c*128+d])
__device__ float g_P[(size_t)NCH*16384];          // 8 MB  chunk propagators
__device__ float g_d[NCH*128];                    // chunk offsets
__device__ float g_cb[NCH*128];                   // chunk-start states
__device__ float g_c[NTOK*128];                   // 4 MB

// ---------------- f32x2 helpers ----------------
__device__ __forceinline__ unsigned long long dupf(float a) {
    unsigned long long r;
    asm("mov.b64 %0, {%1, %1};" : "=l"(r) : "f"(a));
    return r;
}
__device__ __forceinline__ void fma2(unsigned long long& c, unsigned long long a, unsigned long long b) {
    asm("fma.rn.f32x2 %0, %1, %2, %0;" : "+l"(c) : "l"(a), "l"(b));
}
__device__ __forceinline__ void unpk(unsigned long long v, float& lo, float& hi) {
    asm("mov.b64 {%0, %1}, %2;" : "=f"(lo), "=f"(hi) : "l"(v));
}

// ---------------- merged prep: build_M | concat | wd2 | wu3 ----------------
__global__ __launch_bounds__(256) void prep_all(
        const float* __restrict__ Wq, const float* __restrict__ bq,
        const float* __restrict__ Wk, const float* __restrict__ bk,
        const float* __restrict__ Wv, const float* __restrict__ bv,
        const float* __restrict__ Wa, const float* __restrict__ ba,
        const float* __restrict__ Wd, const float* __restrict__ Wu) {
    __shared__ float sd[128][33];
    __shared__ float su[32][128];
    int bid = blockIdx.x;
    int tid = threadIdx.x;
    if (bid < 64) {
        int j = bid;
        int c0 = tid >> 1;
        int dbase = (tid & 1) * 64;
        float acc[64];
        #pragma unroll
        for (int i = 0; i < 64; i++) acc[i] = 0.f;
        for (int vp = 0; vp < 2; vp++) {
            for (int l = tid; l < 128*32; l += 256) {
                int c = l >> 5, v = l & 31;
                sd[c][v] = Wd[(size_t)c*4096 + j*64 + vp*32 + v];
            }
            for (int l = tid; l < 32*128; l += 256) {
                int v = l >> 7, d = l & 127;
                su[v][d] = Wu[(size_t)(j*64 + vp*32 + v)*128 + d];
            }
            __syncthreads();
            #pragma unroll 8
            for (int v = 0; v < 32; v++) {
                float a = sd[c0][v];
                #pragma unroll
                for (int d = 0; d < 64; d++)
                    acc[d] += a * su[v][dbase + d];
            }
            __syncthreads();
        }
        for (int d = 0; d < 64; d++)
            g_MT[(size_t)(c0*128 + dbase + d)*64 + j] = acc[d];
    } else if (bid < 1088) {
        int idx = (bid - 64)*256 + tid;
        int r = idx >> 10, cc = idx & 1023;
        float w;
        if (r < 64)       w = Wq[r*DMM + cc];
        else if (r < 128) w = Wk[(r-64)*DMM + cc];
        else if (r < 192) w = Wv[(r-128)*DMM + cc];
        else              w = Wa[(r-192)*DMM + cc];
        g_Wcat[idx] = w;
        if (bid == 64) {
            g_bcat[tid] = (tid < 64) ? bq[tid] :
                          (tid < 128) ? bk[tid-64] :
                          (tid < 192) ? bv[tid-128] : ba[tid-192];
        }
    } else if (bid < 3136) {
        int idx = (bid - 1088)*256 + tid;       // over 128*4096
        int c = idx >> 12, rest = idx & 4095;
        int j = rest >> 6, v = rest & 63;
        g_Wd2[(size_t)((c<<6) + v)*64 + j] = Wd[idx];
    } else {
        int idx = (bid - 3136)*256 + tid;       // over 4096*128
        int kv = idx >> 7, c = idx & 127;
        int k = kv >> 6, v = kv & 63;
        g_Wu3[(size_t)(v*128 + c)*64 + k] = Wu[idx];
    }
}

// ---------------- projection GEMM (K=1024), fused split/sigmoid epilogue ----------------
__global__ void __launch_bounds__(256) gemm_proj(const float* __restrict__ A,
                                                 const float* __restrict__ B,
                                                 int M, int N, int K) {
    __shared__ __align__(16) float As[2][16][132];
    __shared__ __align__(16) float Bs[2][16][132];
    int tid = threadIdx.x;
    int tx = tid & 15, ty = tid >> 4;
    int row0 = blockIdx.y*128, col0 = blockIdx.x*128;
    int lr = tid >> 1;
    int lk = (tid & 1) * 8;
    const float* Ap = A + (size_t)(row0+lr)*K + lk;
    const float* Bp = B + (size_t)(col0+lr)*K + lk;

    unsigned long long acc[8][4];
    #pragma unroll
    for (int i = 0; i < 8; i++)
        #pragma unroll
        for (int j = 0; j < 4; j++) acc[i][j] = 0ULL;

    int nt = K >> 4;
    {
        float4 a0 = *(const float4*)(Ap + 0);
        float4 a1 = *(const float4*)(Ap + 4);
        float4 b0 = *(const float4*)(Bp + 0);
        float4 b1 = *(const float4*)(Bp + 4);
        As[0][lk+0][lr]=a0.x; As[0][lk+1][lr]=a0.y; As[0][lk+2][lr]=a0.z; As[0][lk+3][lr]=a0.w;
        As[0][lk+4][lr]=a1.x; As[0][lk+5][lr]=a1.y; As[0][lk+6][lr]=a1.z; As[0][lk+7][lr]=a1.w;
        Bs[0][lk+0][lr]=b0.x; Bs[0][lk+1][lr]=b0.y; Bs[0][lk+2][lr]=b0.z; Bs[0][lk+3][lr]=b0.w;
        Bs[0][lk+4][lr]=b1.x; Bs[0][lk+5][lr]=b1.y; Bs[0][lk+6][lr]=b1.z; Bs[0][lk+7][lr]=b1.w;
    }
    __syncthreads();

    #pragma unroll 1
    for (int t = 0; t < nt; t++) {
        int cur = t & 1;
        float4 a0, a1, b0, b1;
        if (t + 1 < nt) {
            int k0 = (t+1) << 4;
            a0 = *(const float4*)(Ap + k0);
            a1 = *(const float4*)(Ap + k0 + 4);
            b0 = *(const float4*)(Bp + k0);
            b1 = *(const float4*)(Bp + k0 + 4);
        }
        #pragma unroll
        for (int kk = 0; kk < 16; kk++) {
            float4 af0 = *(const float4*)&As[cur][kk][ty*8];
            float4 af1 = *(const float4*)&As[cur][kk][ty*8 + 4];
            ulonglong2 bv0 = *(const ulonglong2*)&Bs[cur][kk][tx*8];
            ulonglong2 bv1 = *(const ulonglong2*)&Bs[cur][kk][tx*8 + 4];
            float av[8] = {af0.x, af0.y, af0.z, af0.w, af1.x, af1.y, af1.z, af1.w};
            unsigned long long bw[4] = {bv0.x, bv0.y, bv1.x, bv1.y};
            #pragma unroll
            for (int i = 0; i < 8; i++) {
                unsigned long long ad = dupf(av[i]);
                #pragma unroll
                for (int j = 0; j < 4; j++) fma2(acc[i][j], ad, bw[j]);
            }
        }
        if (t + 1 < nt) {
            int nb = cur ^ 1;
            As[nb][lk+0][lr]=a0.x; As[nb][lk+1][lr]=a0.y; As[nb][lk+2][lr]=a0.z; As[nb][lk+3][lr]=a0.w;
            As[nb][lk+4][lr]=a1.x; As[nb][lk+5][lr]=a1.y; As[nb][lk+6][lr]=a1.z; As[nb][lk+7][lr]=a1.w;
            Bs[nb][lk+0][lr]=b0.x; Bs[nb][lk+1][lr]=b0.y; Bs[nb][lk+2][lr]=b0.z; Bs[nb][lk+3][lr]=b0.w;
            Bs[nb][lk+4][lr]=b1.x; Bs[nb][lk+5][lr]=b1.y; Bs[nb][lk+6][lr]=b1.z; Bs[nb][lk+7][lr]=b1.w;
        }
        __syncthreads();
    }

    #pragma unroll
    for (int i = 0; i < 8; i++) {
        int m = row0 + ty*8 + i;
        float4 o0, o1;
        unpk(acc[i][0], o0.x, o0.y); unpk(acc[i][1], o0.z, o0.w);
        unpk(acc[i][2], o1.x, o1.y); unpk(acc[i][3], o1.z, o1.w);
        int n0 = col0 + tx*8;
        const float* bp = g_bcat + n0;
        o0.x += bp[0]; o0.y += bp[1]; o0.z += bp[2]; o0.w += bp[3];
        o1.x += bp[4]; o1.y += bp[5]; o1.z += bp[6]; o1.w += bp[7];
        int blk = n0 >> 6;
        int w = n0 & 63;
        float* base = (blk == 0) ? g_q : (blk == 1) ? g_k : (blk == 2) ? g_v : g_alpha;
        if (blk == 3) {
            o0.x = 1.f/(1.f+expf(-o0.x)); o0.y = 1.f/(1.f+expf(-o0.y));
            o0.z = 1.f/(1.f+expf(-o0.z)); o0.w = 1.f/(1.f+expf(-o0.w));
            o1.x = 1.f/(1.f+expf(-o1.x)); o1.y = 1.f/(1.f+expf(-o1.y));
            o1.z = 1.f/(1.f+expf(-o1.z)); o1.w = 1.f/(1.f+expf(-o1.w));
        }
        *(float4*)(base + (size_t)m*64 + w)     = o0;
        *(float4*)(base + (size_t)m*64 + w + 4) = o1;
    }
}

// ---------------- K=64 GEMM with fused epilogues ----------------
// C[M,N] = A[M,64] @ B[N,64]^T, tile 128x128, 256 threads, one-shot smem.
// MODE 0: plain store (N passed). MODE 1: bin epilogue (y*v -> g_bin).
// MODE 2: o epilogue (G*c -> out, one v per col-tile).
template<int MODE>
__global__ void __launch_bounds__(256, 2) gemmK64(const float* __restrict__ A,
                                                  const float* __restrict__ B,
                                                  float* __restrict__ C, int N) {
    extern __shared__ __align__(16) float sm[];
    float* As = sm;             // [64][132] k-major: As[k*132 + m]
    float* Bs = sm + 64*132;
    int tid = threadIdx.x;
    int tx = tid & 15, ty = tid >> 4;
    int row0 = blockIdx.y*128, col0 = blockIdx.x*128;
    int lr = tid >> 1, kh = (tid & 1)*32;
    {
        const float4* Ap = (const float4*)(A + (size_t)(row0+lr)*64 + kh);
        const float4* Bp = (const float4*)(B + (size_t)(col0+lr)*64 + kh);
        #pragma unroll
        for (int i = 0; i < 8; i++) {
            float4 a = Ap[i];
            float4 b = Bp[i];
            int k0 = kh + i*4;
            As[(k0+0)*132+lr]=a.x; As[(k0+1)*132+lr]=a.y; As[(k0+2)*132+lr]=a.z; As[(k0+3)*132+lr]=a.w;
            Bs[(k0+0)*132+lr]=b.x; Bs[(k0+1)*132+lr]=b.y; Bs[(k0+2)*132+lr]=b.z; Bs[(k0+3)*132+lr]=b.w;
        }
    }
    __syncthreads();

    unsigned long long acc[8][4];
    #pragma unroll
    for (int i = 0; i < 8; i++)
        #pragma unroll
        for (int j = 0; j < 4; j++) acc[i][j] = 0ULL;

    #pragma unroll 8
    for (int k = 0; k < 64; k++) {
        float4 af0 = *(const float4*)&As[k*132 + ty*8];
        float4 af1 = *(const float4*)&As[k*132 + ty*8 + 4];
        ulonglong2 bv0 = *(const ulonglong2*)&Bs[k*132 + tx*8];
        ulonglong2 bv1 = *(const ulonglong2*)&Bs[k*132 + tx*8 + 4];
        float av[8] = {af0.x, af0.y, af0.z, af0.w, af1.x, af1.y, af1.z, af1.w};
        unsigned long long bw[4] = {bv0.x, bv0.y, bv1.x, bv1.y};
        #pragma unroll
        for (int i = 0; i < 8; i++) {
            unsigned long long ad = dupf(av[i]);
            #pragma unroll
            for (int j = 0; j < 4; j++) fma2(acc[i][j], ad, bw[j]);
        }
    }

    // unpack accumulators
    float o[8][8];
    #pragma unroll
    for (int i = 0; i < 8; i++) {
        unpk(acc[i][0], o[i][0], o[i][1]);
        unpk(acc[i][1], o[i][2], o[i][3]);
        unpk(acc[i][2], o[i][4], o[i][5]);
        unpk(acc[i][3], o[i][6], o[i][7]);
    }

    if (MODE == 0) {
        #pragma unroll
        for (int i = 0; i < 8; i++) {
            int m = row0 + ty*8 + i;
            *(float4*)(C + (size_t)m*N + col0 + tx*8)     = *(float4*)&o[i][0];
            *(float4*)(C + (size_t)m*N + col0 + tx*8 + 4) = *(float4*)&o[i][4];
        }
    } else if (MODE == 1) {
        // b_in[t, c] = sum_v y[t, c*64+v]*v[t,v]; tile covers c = col0/64, col0/64+1
        __syncthreads();
        float* sv  = sm;                 // [128][68]
        float* red = sm + 128*68;        // [128][17]
        {
            const float4* vp = (const float4*)(g_v + (size_t)(row0+lr)*64 + kh);
            #pragma unroll
            for (int i = 0; i < 8; i++)
                *(float4*)&sv[lr*68 + kh + i*4] = vp[i];
        }
        __syncthreads();
        int vb = (tx & 7)*8;
        #pragma unroll
        for (int i = 0; i < 8; i++) {
            const float* svr = &sv[(ty*8+i)*68 + vb];
            float p = o[i][0]*svr[0] + o[i][1]*svr[1] + o[i][2]*svr[2] + o[i][3]*svr[3]
                    + o[i][4]*svr[4] + o[i][5]*svr[5] + o[i][6]*svr[6] + o[i][7]*svr[7];
            red[(ty*8+i)*17 + tx] = p;
        }
        __syncthreads();
        int m = tid >> 1, cg = tid & 1;
        const float* rr = &red[m*17 + cg*8];
        float s = rr[0]+rr[1]+rr[2]+rr[3]+rr[4]+rr[5]+rr[6]+rr[7];
        g_bin[(size_t)(row0+m)*128 + (col0>>6) + cg] = s;
    } else {
        // o[t, v0] = sum_c G[t, v0*128+c]*cstate[t,c]; v0 = col0>>7
        __syncthreads();
        float* sc  = sm;                 // [128][132]
        float* red = sm + 128*132;       // [128][17]
        {
            int ch = (tid & 1)*64;
            const float4* cp = (const float4*)(g_c + (size_t)(row0+lr)*128 + ch);
            #pragma unroll
            for (int i = 0; i < 16; i++)
                *(float4*)&sc[lr*132 + ch + i*4] = cp[i];
        }
        __syncthreads();
        #pragma unroll
        for (int i = 0; i < 8; i++) {
            const float* scr = &sc[(ty*8+i)*132 + tx*8];
            float p = o[i][0]*scr[0] + o[i][1]*scr[1] + o[i][2]*scr[2] + o[i][3]*scr[3]
                    + o[i][4]*scr[4] + o[i][5]*scr[5] + o[i][6]*scr[6] + o[i][7]*scr[7];
            red[(ty*8+i)*17 + tx] = p;
        }
        __syncthreads();
        if (tid < 128) {
            const float* rr = &red[tid*17];
            float s = 0.f;
            #pragma unroll
            for (int x = 0; x < 16; x++) s += rr[x];
            C[(size_t)(row0+tid)*64 + (col0>>7)] = s;
        }
    }
}

// ---------------- pass A: per-chunk propagator P and offset d ----------------
__global__ __launch_bounds__(512) void passA_kern() {
    extern __shared__ float sm[];
    float* At = sm;                        // [128][132] transposed
    float* Ps = sm + 128*132;              // [2][128][132]
    float* ds = sm + 3*128*132;            // [2][128]
    int tid = threadIdx.x;
    int chunk = blockIdx.x;
    int b = chunk >> 5, ci = chunk & 31;
    size_t tokBase = (size_t)b*SS + (size_t)ci*CHL;

    for (int idx = tid; idx < 128*132; idx += 512) {
        int r = idx/132, cc = idx - r*132;
        Ps[idx] = (r == cc) ? 1.f : 0.f;
        Ps[128*132 + idx] = 0.f;
    }
    if (tid < 128) { ds[tid] = 0.f; ds[128+tid] = 0.f; }

    int lr = tid >> 2;
    int kq = (tid & 3) * 32;
    float4 rA[8];
    {
        const float4* A0 = (const float4*)(g_A + tokBase*16384);
        #pragma unroll
        for (int i = 0; i < 8; i++) rA[i] = A0[lr*32 + (tid&3)*8 + i];
    }
    __syncthreads();

    int tx = tid & 31, ty = tid >> 5;
    int r2 = tid >> 2, q2 = tid & 3;
    int cur = 0;
    for (int s = 0; s < CHL; s++) {
        #pragma unroll
        for (int i = 0; i < 8; i++) {
            float4 v = rA[i];
            int k0 = kq + i*4;
            At[(k0+0)*132 + lr] = v.x;
            At[(k0+1)*132 + lr] = v.y;
            At[(k0+2)*132 + lr] = v.z;
            At[(k0+3)*132 + lr] = v.w;
        }
        __syncthreads();
        if (s + 1 < CHL) {
            const float4* An = (const float4*)(g_A + (tokBase + s + 1)*16384);
            #pragma unroll
            for (int i = 0; i < 8; i++) rA[i] = An[lr*32 + (tid&3)*8 + i];
        }
        unsigned long long acc[8][2];
        #pragma unroll
        for (int i = 0; i < 8; i++) { acc[i][0] = 0ULL; acc[i][1] = 0ULL; }
        float dacc = 0.f;
        const float* Pc = Ps + cur*128*132;
        const float* dc = ds + cur*128;
        #pragma unroll 4
        for (int k = 0; k < 128; k++) {
            float4 a0 = *(const float4*)&At[k*132 + ty*8];
            float4 a1 = *(const float4*)&At[k*132 + ty*8 + 4];
            ulonglong2 bb = *(const ulonglong2*)&Pc[k*132 + tx*4];
            float av[8] = {a0.x, a0.y, a0.z, a0.w, a1.x, a1.y, a1.z, a1.w};
            #pragma unroll
            for (int i = 0; i < 8; i++) {
                unsigned long long ad = dupf(av[i]);
                fma2(acc[i][0], ad, bb.x);
                fma2(acc[i][1], ad, bb.y);
            }
            if ((k >> 5) == q2) dacc += At[k*132 + r2] * dc[k];
        }
        dacc += __shfl_xor_sync(0xffffffffu, dacc, 1);
        dacc += __shfl_xor_sync(0xffffffffu, dacc, 2);
        float* Pn = Ps + (cur^1)*128*132;
        #pragma unroll
        for (int i = 0; i < 8; i++) {
            float4 o;
            unpk(acc[i][0], o.x, o.y); unpk(acc[i][1], o.z, o.w);
            *(float4*)&Pn[(ty*8 + i)*132 + tx*4] = o;
        }
        if (q2 == 0)
            ds[(cur^1)*128 + r2] = dacc + g_bin[(tokBase + s)*128 + r2];
        __syncthreads();
        cur ^= 1;
    }
    const float* Pf = Ps + cur*128*132;
    for (int idx = tid; idx < 16384; idx += 512) {
        int r = idx >> 7, cc = idx & 127;
        g_P[(size_t)chunk*16384 + idx] = Pf[r*132 + cc];
    }
    if (tid < 128) g_d[chunk*128 + tid] = ds[cur*128 + tid];
}

// ---------------- pass B: cross-chunk scan (per batch) ----------------
__global__ __launch_bounds__(512) void passB_kern() {
    int b = blockIdx.x;
    int tid = threadIdx.x;
    int r = tid >> 2, dq = tid & 3;
    __shared__ float cv[128], nv[128];
    if (tid < 128) cv[tid] = 0.f;
    __syncthreads();
    for (int i = 0; i < SS/CHL; i++) {
        int chunk = b*(SS/CHL) + i;
        if (tid < 128) g_cb[chunk*128 + tid] = cv[tid];
        __syncthreads();
        const float4* Pr = (const float4*)(g_P + (size_t)chunk*16384);
        float acc = 0.f;
        #pragma unroll
        for (int j = 0; j < 8; j++) {
            int jj = (j + 2*dq) & 7;
            float4 pv = Pr[tid*8 + jj];
            float4 c4 = *(const float4*)&cv[dq*32 + jj*4];
            acc += pv.x*c4.x + pv.y*c4.y + pv.z*c4.z + pv.w*c4.w;
        }
        acc += __shfl_xor_sync(0xffffffffu, acc, 1);
        acc += __shfl_xor_sync(0xffffffffu, acc, 2);
        if (dq == 0) nv[r] = acc + g_d[chunk*128 + r];
        __syncthreads();
        if (tid < 128) cv[tid] = nv[tid];
        __syncthreads();
    }
}

// ---------------- pass C: within-chunk recurrence ----------------
__global__ __launch_bounds__(512) void passC_kern() {
    int chunk = blockIdx.x;
    int b = chunk >> 5, ci = chunk & 31;
    size_t tokBase = (size_t)b*SS + (size_t)ci*CHL;
    int tid = threadIdx.x;
    int r = tid >> 2, dq = tid & 3;
    __shared__ float cs[2][128];
    if (tid < 128) cs[0][tid] = g_cb[chunk*128 + tid];
    __syncthreads();

    const float4* Ab = (const float4*)(g_A + tokBase*16384);
    float4 buf[8];
    #pragma unroll
    for (int i = 0; i < 8; i++) buf[i] = Ab[tid*8 + ((i + 2*dq) & 7)];

    int p = 0;
    for (int s = 0; s < CHL; s++) {
        float4 nbuf[8];
        if (s + 1 < CHL) {
            const float4* An = Ab + (size_t)(s+1)*4096;
            #pragma unroll
            for (int i = 0; i < 8; i++) nbuf[i] = An[tid*8 + ((i + 2*dq) & 7)];
        }
        float acc = 0.f;
        #pragma unroll
        for (int i = 0; i < 8; i++) {
            int ii = (i + 2*dq) & 7;
            float4 cv = *(const float4*)&cs[p][dq*32 + ii*4];
            acc += buf[i].x*cv.x + buf[i].y*cv.y + buf[i].z*cv.z + buf[i].w*cv.w;
        }
        acc += __shfl_xor_sync(0xffffffffu, acc, 1);
        acc += __shfl_xor_sync(0xffffffffu, acc, 2);
        if (dq == 0) {
            float cn = acc + g_bin[(tokBase + s)*128 + r];
            cs[p ^ 1][r] = cn;
            g_c[(tokBase + s)*128 + r] = cn;
        }
        __syncthreads();
        p ^= 1;
        #pragma unroll
        for (int i = 0; i < 8; i++) buf[i] = nbuf[i];
    }
}

// ---------------- host launcher ----------------
extern "C" void kernel_launch(void* const* d_in, const int* in_sizes, int n_in,
                              void* d_out, int out_size) {
    const float* x   = (const float*)d_in[0];
    const float* Wq  = (const float*)d_in[1];
    const float* bq  = (const float*)d_in[2];
    const float* Wk  = (const float*)d_in[3];
    const float* bk  = (const float*)d_in[4];
    const float* Wv  = (const float*)d_in[5];
    const float* bv  = (const float*)d_in[6];
    const float* Wa  = (const float*)d_in[7];
    const float* ba  = (const float*)d_in[8];
    const float* Wdn = (const float*)d_in[9];
    const float* Wup = (const float*)d_in[10];
    float* out = (float*)d_out;

    float *pA, *pAlpha, *pMT, *pWcat, *pQ, *pK, *pWd2, *pWu3;
    cudaGetSymbolAddress((void**)&pA,    g_A);
    cudaGetSymbolAddress((void**)&pAlpha,g_alpha);
    cudaGetSymbolAddress((void**)&pMT,   g_MT);
    cudaGetSymbolAddress((void**)&pWcat, g_Wcat);
    cudaGetSymbolAddress((void**)&pQ,    g_q);
    cudaGetSymbolAddress((void**)&pK,    g_k);
    cudaGetSymbolAddress((void**)&pWd2,  g_Wd2);
    cudaGetSymbolAddress((void**)&pWu3,  g_Wu3);

    static const int PASSA_SMEM = (128*132 + 2*128*132 + 2*128) * 4;
    cudaFuncSetAttribute(passA_kern, cudaFuncAttributeMaxDynamicSharedMemorySize, PASSA_SMEM);

    const int SM_GEMM = 2*64*132*4;                       // 67.6 KB (mode 0)
    const int SM_BIN  = (128*68 + 128*17)*4 < SM_GEMM ? SM_GEMM : (128*68 + 128*17)*4;
    const int SM_O    = (128*132 + 128*17)*4;             // 76.3 KB
    cudaFuncSetAttribute(gemmK64<0>, cudaFuncAttributeMaxDynamicSharedMemorySize, SM_GEMM);
    cudaFuncSetAttribute(gemmK64<1>, cudaFuncAttributeMaxDynamicSharedMemorySize, SM_BIN);
    cudaFuncSetAttribute(gemmK64<2>, cudaFuncAttributeMaxDynamicSharedMemorySize, SM_O);

    // 1. merged weight prep
    prep_all<<<5184, 256>>>(Wq, bq, Wk, bk, Wv, bv, Wa, ba, Wdn, Wup);
    // 2. fused projection + split + sigmoid
    gemm_proj<<<dim3(2, 64), 256>>>(x, pWcat, NTOK, 256, DMM);
    // 3. bin GEMM: y = k @ Wd2^T fused with v-contraction -> g_bin
    gemmK64<1><<<dim3(64, 64), 256, SM_BIN>>>(pK, pWd2, nullptr, 8192);
    // 4. A = alpha @ MT^T  [8192 x 16384]   <-- ncu capture slot
    gemmK64<0><<<dim3(128, 64), 256, SM_GEMM>>>(pAlpha, pMT, pA, 16384);
    // 5. chunk propagators + offsets
    passA_kern<<<NCH, 512, PASSA_SMEM>>>();
    // 6. cross-chunk scan
    passB_kern<<<BB, 512>>>();
    // 7. within-chunk recurrence
    passC_kern<<<NCH, 512>>>();
    // 8. o GEMM: G = q @ Wu3^T fused with c-contraction -> out
    gemmK64<2><<<dim3(64, 64), 256, SM_O>>>(pQ, pWu3, out, 8192);
}

// round 8
// speedup vs baseline: 1.7654x; 1.3100x over previous
#include <cuda_runtime.h>
#include <cuda_bf16.h>
#include <math.h>
#include <stdint.h>

#define BB 4
#define SS 2048
#define DMM 1024
#define NTOK (BB*SS)          /* 8192 */
#define CHL 64
#define NCH (NTOK/CHL)        /* 128 */

// ---------------- scratch ----------------
__device__ float g_Wcat[256*DMM];
__device__ float g_bcat[256];
__device__ float g_v[NTOK*64];
__device__ __nv_bfloat16 g_qh[NTOK*64], g_ql[NTOK*64];
__device__ __nv_bfloat16 g_kh[NTOK*64], g_kl[NTOK*64];
__device__ __nv_bfloat16 g_ah[NTOK*64], g_al[NTOK*64];
__device__ __nv_bfloat16 g_MTh[16384*64], g_MTl[16384*64];   // [(c*128+d)][j]
__device__ __nv_bfloat16 g_Wd2h[8192*64], g_Wd2l[8192*64];   // [(c*64+v)][j]
__device__ __nv_bfloat16 g_Wu3h[8192*64], g_Wu3l[8192*64];   // [(v*128+c)][k]
__device__ float g_bin[NTOK*128];
__device__ float g_A[(size_t)NTOK*16384];                    // 512 MB [t][c*128+d]
__device__ float g_P[(size_t)NCH*16384];
__device__ float g_d[NCH*128];
__device__ float g_cb[NCH*128];
__device__ float g_c[NTOK*128];

// ---------------- f32x2 helpers ----------------
__device__ __forceinline__ unsigned long long dupf(float a) {
    unsigned long long r;
    asm("mov.b64 %0, {%1, %1};" : "=l"(r) : "f"(a));
    return r;
}
__device__ __forceinline__ void fma2(unsigned long long& c, unsigned long long a, unsigned long long b) {
    asm("fma.rn.f32x2 %0, %1, %2, %0;" : "+l"(c) : "l"(a), "l"(b));
}
__device__ __forceinline__ void unpk(unsigned long long v, float& lo, float& hi) {
    asm("mov.b64 {%0, %1}, %2;" : "=f"(lo), "=f"(hi) : "l"(v));
}

// ---------------- mma helpers ----------------
__device__ __forceinline__ uint32_t smem_u32(const void* p) {
    uint32_t a;
    asm("{ .reg .u64 t; cvta.to.shared.u64 t, %1; cvt.u32.u64 %0, t; }" : "=r"(a) : "l"(p));
    return a;
}
#define LDSM4(r, addr) \
    asm volatile("ldmatrix.sync.aligned.m8n8.x4.shared.b16 {%0,%1,%2,%3}, [%4];" \
        : "=r"((r)[0]), "=r"((r)[1]), "=r"((r)[2]), "=r"((r)[3]) : "r"(addr))
#define MMA16816(d, a, b0, b1) \
    asm volatile("mma.sync.aligned.m16n8k16.row.col.f32.bf16.bf16.f32 " \
        "{%0,%1,%2,%3}, {%4,%5,%6,%7}, {%8,%9}, {%0,%1,%2,%3};" \
        : "+f"((d)[0]), "+f"((d)[1]), "+f"((d)[2]), "+f"((d)[3]) \
        : "r"((a)[0]), "r"((a)[1]), "r"((a)[2]), "r"((a)[3]), "r"(b0), "r"(b1))

__device__ __forceinline__ void split_bf16(float x, __nv_bfloat16& h, __nv_bfloat16& l) {
    h = __float2bfloat16(x);
    l = __float2bfloat16(x - __bfloat162float(h));
}

// ---------------- merged prep: build_M | concat | wd2 | wu3 (bf16-split outputs) ----------------
__global__ __launch_bounds__(256) void prep_all(
        const float* __restrict__ Wq, const float* __restrict__ bq,
        const float* __restrict__ Wk, const float* __restrict__ bk,
        const float* __restrict__ Wv, const float* __restrict__ bv,
        const float* __restrict__ Wa, const float* __restrict__ ba,
        const float* __restrict__ Wd, const float* __restrict__ Wu) {
    __shared__ float sd[128][33];
    __shared__ float su[32][128];
    int bid = blockIdx.x;
    int tid = threadIdx.x;
    if (bid < 64) {
        int j = bid;
        int c0 = tid >> 1;
        int dbase = (tid & 1) * 64;
        float acc[64];
        #pragma unroll
        for (int i = 0; i < 64; i++) acc[i] = 0.f;
        for (int vp = 0; vp < 2; vp++) {
            for (int l = tid; l < 128*32; l += 256) {
                int c = l >> 5, v = l & 31;
                sd[c][v] = Wd[(size_t)c*4096 + j*64 + vp*32 + v];
            }
            for (int l = tid; l < 32*128; l += 256) {
                int v = l >> 7, d = l & 127;
                su[v][d] = Wu[(size_t)(j*64 + vp*32 + v)*128 + d];
            }
            __syncthreads();
            #pragma unroll 8
            for (int v = 0; v < 32; v++) {
                float a = sd[c0][v];
                #pragma unroll
                for (int d = 0; d < 64; d++)
                    acc[d] += a * su[v][dbase + d];
            }
            __syncthreads();
        }
        for (int d = 0; d < 64; d++) {
            __nv_bfloat16 h, l;
            split_bf16(acc[d], h, l);
            size_t pos = (size_t)(c0*128 + dbase + d)*64 + j;
            g_MTh[pos] = h; g_MTl[pos] = l;
        }
    } else if (bid < 1088) {
        int idx = (bid - 64)*256 + tid;
        int r = idx >> 10, cc = idx & 1023;
        float w;
        if (r < 64)       w = Wq[r*DMM + cc];
        else if (r < 128) w = Wk[(r-64)*DMM + cc];
        else if (r < 192) w = Wv[(r-128)*DMM + cc];
        else              w = Wa[(r-192)*DMM + cc];
        g_Wcat[idx] = w;
        if (bid == 64) {
            g_bcat[tid] = (tid < 64) ? bq[tid] :
                          (tid < 128) ? bk[tid-64] :
                          (tid < 192) ? bv[tid-128] : ba[tid-192];
        }
    } else if (bid < 3136) {
        int idx = (bid - 1088)*256 + tid;       // over 128*4096
        int c = idx >> 12, rest = idx & 4095;
        int j = rest >> 6, v = rest & 63;
        __nv_bfloat16 h, l;
        split_bf16(Wd[idx], h, l);
        size_t pos = (size_t)((c<<6) + v)*64 + j;
        g_Wd2h[pos] = h; g_Wd2l[pos] = l;
    } else {
        int idx = (bid - 3136)*256 + tid;       // over 4096*128
        int kv = idx >> 7, c = idx & 127;
        int k = kv >> 6, v = kv & 63;
        __nv_bfloat16 h, l;
        split_bf16(Wu[idx], h, l);
        size_t pos = (size_t)(v*128 + c)*64 + k;
        g_Wu3h[pos] = h; g_Wu3l[pos] = l;
    }
}

// ---------------- projection GEMM (K=1024), split/sigmoid/bf16 epilogue ----------------
__global__ void __launch_bounds__(256) gemm_proj(const float* __restrict__ A,
                                                 const float* __restrict__ B,
                                                 int M, int N, int K) {
    __shared__ __align__(16) float As[2][16][132];
    __shared__ __align__(16) float Bs[2][16][132];
    int tid = threadIdx.x;
    int tx = tid & 15, ty = tid >> 4;
    int row0 = blockIdx.y*128, col0 = blockIdx.x*128;
    int lr = tid >> 1;
    int lk = (tid & 1) * 8;
    const float* Ap = A + (size_t)(row0+lr)*K + lk;
    const float* Bp = B + (size_t)(col0+lr)*K + lk;

    unsigned long long acc[8][4];
    #pragma unroll
    for (int i = 0; i < 8; i++)
        #pragma unroll
        for (int j = 0; j < 4; j++) acc[i][j] = 0ULL;

    int nt = K >> 4;
    {
        float4 a0 = *(const float4*)(Ap + 0);
        float4 a1 = *(const float4*)(Ap + 4);
        float4 b0 = *(const float4*)(Bp + 0);
        float4 b1 = *(const float4*)(Bp + 4);
        As[0][lk+0][lr]=a0.x; As[0][lk+1][lr]=a0.y; As[0][lk+2][lr]=a0.z; As[0][lk+3][lr]=a0.w;
        As[0][lk+4][lr]=a1.x; As[0][lk+5][lr]=a1.y; As[0][lk+6][lr]=a1.z; As[0][lk+7][lr]=a1.w;
        Bs[0][lk+0][lr]=b0.x; Bs[0][lk+1][lr]=b0.y; Bs[0][lk+2][lr]=b0.z; Bs[0][lk+3][lr]=b0.w;
        Bs[0][lk+4][lr]=b1.x; Bs[0][lk+5][lr]=b1.y; Bs[0][lk+6][lr]=b1.z; Bs[0][lk+7][lr]=b1.w;
    }
    __syncthreads();

    #pragma unroll 1
    for (int t = 0; t < nt; t++) {
        int cur = t & 1;
        float4 a0, a1, b0, b1;
        if (t + 1 < nt) {
            int k0 = (t+1) << 4;
            a0 = *(const float4*)(Ap + k0);
            a1 = *(const float4*)(Ap + k0 + 4);
            b0 = *(const float4*)(Bp + k0);
            b1 = *(const float4*)(Bp + k0 + 4);
        }
        #pragma unroll
        for (int kk = 0; kk < 16; kk++) {
            float4 af0 = *(const float4*)&As[cur][kk][ty*8];
            float4 af1 = *(const float4*)&As[cur][kk][ty*8 + 4];
            ulonglong2 bv0 = *(const ulonglong2*)&Bs[cur][kk][tx*8];
            ulonglong2 bv1 = *(const ulonglong2*)&Bs[cur][kk][tx*8 + 4];
            float av[8] = {af0.x, af0.y, af0.z, af0.w, af1.x, af1.y, af1.z, af1.w};
            unsigned long long bw[4] = {bv0.x, bv0.y, bv1.x, bv1.y};
            #pragma unroll
            for (int i = 0; i < 8; i++) {
                unsigned long long ad = dupf(av[i]);
                #pragma unroll
                for (int j = 0; j < 4; j++) fma2(acc[i][j], ad, bw[j]);
            }
        }
        if (t + 1 < nt) {
            int nb = cur ^ 1;
            As[nb][lk+0][lr]=a0.x; As[nb][lk+1][lr]=a0.y; As[nb][lk+2][lr]=a0.z; As[nb][lk+3][lr]=a0.w;
            As[nb][lk+4][lr]=a1.x; As[nb][lk+5][lr]=a1.y; As[nb][lk+6][lr]=a1.z; As[nb][lk+7][lr]=a1.w;
            Bs[nb][lk+0][lr]=b0.x; Bs[nb][lk+1][lr]=b0.y; Bs[nb][lk+2][lr]=b0.z; Bs[nb][lk+3][lr]=b0.w;
            Bs[nb][lk+4][lr]=b1.x; Bs[nb][lk+5][lr]=b1.y; Bs[nb][lk+6][lr]=b1.z; Bs[nb][lk+7][lr]=b1.w;
        }
        __syncthreads();
    }

    #pragma unroll
    for (int i = 0; i < 8; i++) {
        int m = row0 + ty*8 + i;
        float val[8];
        unpk(acc[i][0], val[0], val[1]); unpk(acc[i][1], val[2], val[3]);
        unpk(acc[i][2], val[4], val[5]); unpk(acc[i][3], val[6], val[7]);
        int n0 = col0 + tx*8;
        const float* bp = g_bcat + n0;
        #pragma unroll
        for (int e = 0; e < 8; e++) val[e] += bp[e];
        int blk = n0 >> 6;
        int w = n0 & 63;
        if (blk == 2) {
            *(float4*)(g_v + (size_t)m*64 + w)     = *(float4*)&val[0];
            *(float4*)(g_v + (size_t)m*64 + w + 4) = *(float4*)&val[4];
        } else {
            __nv_bfloat16* bh;
            __nv_bfloat16* bl;
            if (blk == 0)      { bh = g_qh; bl = g_ql; }
            else if (blk == 1) { bh = g_kh; bl = g_kl; }
            else               { bh = g_ah; bl = g_al;
                #pragma unroll
                for (int e = 0; e < 8; e++) val[e] = 1.f/(1.f+expf(-val[e]));
            }
            __nv_bfloat16 h8[8], l8[8];
            #pragma unroll
            for (int e = 0; e < 8; e++) split_bf16(val[e], h8[e], l8[e]);
            *(uint4*)(bh + (size_t)m*64 + w) = *(uint4*)h8;
            *(uint4*)(bl + (size_t)m*64 + w) = *(uint4*)l8;
        }
    }
}

// ---------------- mma.sync bf16-split K=64 GEMM, 128x128 tile, 256 threads ----------------
// D = Ah@Bh^T + Ah@Bl^T + Al@Bh^T (fp32 regs).
// MODE 0: store D to C (row stride 16384) via smem staging.
// MODE 1: bin epilogue: b_in[m,c] = sum_v D[m, c*64+v] * g_v[m,v].
// MODE 2: o epilogue:   out[m, blockIdx.x] = sum_c D[m,c] * g_c[m,c].
#define TILEB 18432              /* 128 rows * 144 B */
#define EPI_OFF (4*TILEB)        /* 73728 */
template<int MODE>
__global__ void __launch_bounds__(256) hgemm(const __nv_bfloat16* __restrict__ Ah,
                                             const __nv_bfloat16* __restrict__ Al,
                                             const __nv_bfloat16* __restrict__ Bh,
                                             const __nv_bfloat16* __restrict__ Bl,
                                             float* __restrict__ C) {
    extern __shared__ __align__(16) char smem[];
    uint32_t sb = smem_u32(smem);
    int tid = threadIdx.x;
    int lane = tid & 31, wid = tid >> 5;
    int gid = lane >> 2, tig = lane & 3;
    int warpM = wid >> 2, warpN = wid & 3;
    int m0 = warpM*64, n0 = warpN*32;
    int row0 = blockIdx.y*128, col0 = blockIdx.x*128;

    // stage 4 operand tiles: [128 rows][64 bf16 = 128B] at 144B row stride
    {
        const uint4* srcs[4] = {
            (const uint4*)(Ah + (size_t)row0*64), (const uint4*)(Al + (size_t)row0*64),
            (const uint4*)(Bh + (size_t)col0*64), (const uint4*)(Bl + (size_t)col0*64) };
        #pragma unroll
        for (int t = 0; t < 4; t++) {
            char* dst = smem + t*TILEB;
            #pragma unroll
            for (int j = 0; j < 4; j++) {
                int idx = tid + j*256;           // 1024 16B chunks
                int r = idx >> 3, ch = idx & 7;
                *(uint4*)(dst + r*144 + ch*16) = srcs[t][idx];
            }
        }
    }
    if (MODE == 1) {
        float* sv = (float*)(smem + EPI_OFF);    // [128][68]
        const float4* vp = (const float4*)(g_v + (size_t)row0*64);
        #pragma unroll
        for (int j = 0; j < 8; j++) {
            int idx = tid + j*256;               // 2048 float4
            int r = idx >> 4, q = idx & 15;
            *(float4*)&sv[r*68 + q*4] = vp[idx];
        }
    }
    if (MODE == 2) {
        float* sc = (float*)(smem + EPI_OFF);    // [128][132]
        const float4* cp = (const float4*)(g_c + (size_t)row0*128);
        #pragma unroll
        for (int j = 0; j < 16; j++) {
            int idx = tid + j*256;               // 4096 float4
            int r = idx >> 5, q = idx & 31;
            *(float4*)&sc[r*132 + q*4] = cp[idx];
        }
    }
    __syncthreads();

    // ldmatrix lane offsets
    int q8 = lane >> 3, i8 = lane & 7;
    uint32_t aLane = (uint32_t)(((q8 & 1)*8 + i8)*144 + (q8 >> 1)*16);
    uint32_t bLane = (uint32_t)(((q8 >> 1)*8 + i8)*144 + (q8 & 1)*16);

    float d[4][4][4];
    #pragma unroll
    for (int mt = 0; mt < 4; mt++)
        #pragma unroll
        for (int nt = 0; nt < 4; nt++)
            #pragma unroll
            for (int e = 0; e < 4; e++) d[mt][nt][e] = 0.f;

    #pragma unroll
    for (int term = 0; term < 3; term++) {
        uint32_t aBase = sb + (term == 2 ? TILEB : 0) + (uint32_t)m0*144 + aLane;
        uint32_t bBase = sb + 2*TILEB + (term == 1 ? TILEB : 0) + (uint32_t)n0*144 + bLane;
        #pragma unroll
        for (int ks = 0; ks < 4; ks++) {
            uint32_t koff = (uint32_t)(ks*32);   // 16 bf16 = 32 B
            uint32_t af[4][4], bf2[2][4];
            #pragma unroll
            for (int mt = 0; mt < 4; mt++)
                LDSM4(af[mt], aBase + mt*16*144 + koff);
            #pragma unroll
            for (int nt2 = 0; nt2 < 2; nt2++)
                LDSM4(bf2[nt2], bBase + nt2*16*144 + koff);
            #pragma unroll
            for (int mt = 0; mt < 4; mt++)
                #pragma unroll
                for (int nt = 0; nt < 4; nt++)
                    MMA16816(d[mt][nt], af[mt], bf2[nt>>1][(nt&1)*2], bf2[nt>>1][(nt&1)*2+1]);
        }
    }
    __syncthreads();     // operands dead; smem reusable

    if (MODE == 0) {
        float* Ds = (float*)smem;                // [128][132]
        #pragma unroll
        for (int mt = 0; mt < 4; mt++) {
            int r0 = m0 + mt*16 + gid, r1 = r0 + 8;
            #pragma unroll
            for (int nt = 0; nt < 4; nt++) {
                int cl = n0 + nt*8 + tig*2;
                *(float2*)&Ds[r0*132 + cl] = make_float2(d[mt][nt][0], d[mt][nt][1]);
                *(float2*)&Ds[r1*132 + cl] = make_float2(d[mt][nt][2], d[mt][nt][3]);
            }
        }
        __syncthreads();
        #pragma unroll
        for (int it = 0; it < 16; it++) {
            int idx = tid + it*256;              // 4096 float4
            int r = idx >> 5, q4 = idx & 31;
            *(float4*)(C + (size_t)(row0 + r)*16384 + col0 + q4*4) =
                *(const float4*)&Ds[r*132 + q4*4];
        }
    } else if (MODE == 1) {
        const float* sv = (const float*)(smem + EPI_OFF);
        float* red = (float*)smem;               // [128][4]
        #pragma unroll
        for (int mt = 0; mt < 4; mt++) {
            int r0 = m0 + mt*16 + gid, r1 = r0 + 8;
            float p0 = 0.f, p1 = 0.f;
            #pragma unroll
            for (int nt = 0; nt < 4; nt++) {
                int v = (n0 + nt*8 + tig*2) & 63;
                p0 += d[mt][nt][0]*sv[r0*68 + v] + d[mt][nt][1]*sv[r0*68 + v + 1];
                p1 += d[mt][nt][2]*sv[r1*68 + v] + d[mt][nt][3]*sv[r1*68 + v + 1];
            }
            p0 += __shfl_xor_sync(0xffffffffu, p0, 1);
            p0 += __shfl_xor_sync(0xffffffffu, p0, 2);
            p1 += __shfl_xor_sync(0xffffffffu, p1, 1);
            p1 += __shfl_xor_sync(0xffffffffu, p1, 2);
            if (tig == 0) { red[r0*4 + warpN] = p0; red[r1*4 + warpN] = p1; }
        }
        __syncthreads();
        if (tid < 128) {
            int cb = blockIdx.x*2;
            float s0 = red[tid*4 + 0] + red[tid*4 + 1];
            float s1 = red[tid*4 + 2] + red[tid*4 + 3];
            g_bin[(size_t)(row0 + tid)*128 + cb]     = s0;
            g_bin[(size_t)(row0 + tid)*128 + cb + 1] = s1;
        }
    } else {
        const float* sc = (const float*)(smem + EPI_OFF);
        float* red = (float*)smem;               // [128][4]
        #pragma unroll
        for (int mt = 0; mt < 4; mt++) {
            int r0 = m0 + mt*16 + gid, r1 = r0 + 8;
            float p0 = 0.f, p1 = 0.f;
            #pragma unroll
            for (int nt = 0; nt < 4; nt++) {
                int c = n0 + nt*8 + tig*2;
                p0 += d[mt][nt][0]*sc[r0*132 + c] + d[mt][nt][1]*sc[r0*132 + c + 1];
                p1 += d[mt][nt][2]*sc[r1*132 + c] + d[mt][nt][3]*sc[r1*132 + c + 1];
            }
            p0 += __shfl_xor_sync(0xffffffffu, p0, 1);
            p0 += __shfl_xor_sync(0xffffffffu, p0, 2);
            p1 += __shfl_xor_sync(0xffffffffu, p1, 1);
            p1 += __shfl_xor_sync(0xffffffffu, p1, 2);
            if (tig == 0) { red[r0*4 + warpN] = p0; red[r1*4 + warpN] = p1; }
        }
        __syncthreads();
        if (tid < 128) {
            float s = red[tid*4+0] + red[tid*4+1] + red[tid*4+2] + red[tid*4+3];
            C[(size_t)(row0 + tid)*64 + blockIdx.x] = s;
        }
    }
}

// ---------------- pass A: per-chunk propagator P and offset d ----------------
__global__ __launch_bounds__(512) void passA_kern() {
    extern __shared__ float sm[];
    float* At = sm;                        // [128][132] transposed
    float* Ps = sm + 128*132;              // [2][128][132]
    float* ds = sm + 3*128*132;            // [2][128]
    int tid = threadIdx.x;
    int chunk = blockIdx.x;
    int b = chunk >> 5, ci = chunk & 31;
    size_t tokBase = (size_t)b*SS + (size_t)ci*CHL;

    for (int idx = tid; idx < 128*132; idx += 512) {
        int r = idx/132, cc = idx - r*132;
        Ps[idx] = (r == cc) ? 1.f : 0.f;
        Ps[128*132 + idx] = 0.f;
    }
    if (tid < 128) { ds[tid] = 0.f; ds[128+tid] = 0.f; }

    int lr = tid >> 2;
    int kq = (tid & 3) * 32;
    float4 rA[8];
    {
        const float4* A0 = (const float4*)(g_A + tokBase*16384);
        #pragma unroll
        for (int i = 0; i < 8; i++) rA[i] = A0[lr*32 + (tid&3)*8 + i];
    }
    __syncthreads();

    int tx = tid & 31, ty = tid >> 5;
    int r2 = tid >> 2, q2 = tid & 3;
    int cur = 0;
    for (int s = 0; s < CHL; s++) {
        #pragma unroll
        for (int i = 0; i < 8; i++) {
            float4 v = rA[i];
            int k0 = kq + i*4;
            At[(k0+0)*132 + lr] = v.x;
            At[(k0+1)*132 + lr] = v.y;
            At[(k0+2)*132 + lr] = v.z;
            At[(k0+3)*132 + lr] = v.w;
        }
        __syncthreads();
        if (s + 1 < CHL) {
            const float4* An = (const float4*)(g_A + (tokBase + s + 1)*16384);
            #pragma unroll
            for (int i = 0; i < 8; i++) rA[i] = An[lr*32 + (tid&3)*8 + i];
        }
        unsigned long long acc[8][2];
        #pragma unroll
        for (int i = 0; i < 8; i++) { acc[i][0] = 0ULL; acc[i][1] = 0ULL; }
        float dacc = 0.f;
        const float* Pc = Ps + cur*128*132;
        const float* dc = ds + cur*128;
        #pragma unroll 4
        for (int k = 0; k < 128; k++) {
            float4 a0 = *(const float4*)&At[k*132 + ty*8];
            float4 a1 = *(const float4*)&At[k*132 + ty*8 + 4];
            ulonglong2 bb = *(const ulonglong2*)&Pc[k*132 + tx*4];
            float av[8] = {a0.x, a0.y, a0.z, a0.w, a1.x, a1.y, a1.z, a1.w};
            #pragma unroll
            for (int i = 0; i < 8; i++) {
                unsigned long long ad = dupf(av[i]);
                fma2(acc[i][0], ad, bb.x);
                fma2(acc[i][1], ad, bb.y);
            }
            if ((k >> 5) == q2) dacc += At[k*132 + r2] * dc[k];
        }
        dacc += __shfl_xor_sync(0xffffffffu, dacc, 1);
        dacc += __shfl_xor_sync(0xffffffffu, dacc, 2);
        float* Pn = Ps + (cur^1)*128*132;
        #pragma unroll
        for (int i = 0; i < 8; i++) {
            float4 o;
            unpk(acc[i][0], o.x, o.y); unpk(acc[i][1], o.z, o.w);
            *(float4*)&Pn[(ty*8 + i)*132 + tx*4] = o;
        }
        if (q2 == 0)
            ds[(cur^1)*128 + r2] = dacc + g_bin[(tokBase + s)*128 + r2];
        __syncthreads();
        cur ^= 1;
    }
    const float* Pf = Ps + cur*128*132;
    for (int idx = tid; idx < 16384; idx += 512) {
        int r = idx >> 7, cc = idx & 127;
        g_P[(size_t)chunk*16384 + idx] = Pf[r*132 + cc];
    }
    if (tid < 128) g_d[chunk*128 + tid] = ds[cur*128 + tid];
}

// ---------------- pass B: cross-chunk scan ----------------
__global__ __launch_bounds__(512) void passB_kern() {
    int b = blockIdx.x;
    int tid = threadIdx.x;
    int r = tid >> 2, dq = tid & 3;
    __shared__ float cv[128], nv[128];
    if (tid < 128) cv[tid] = 0.f;
    __syncthreads();
    for (int i = 0; i < SS/CHL; i++) {
        int chunk = b*(SS/CHL) + i;
        if (tid < 128) g_cb[chunk*128 + tid] = cv[tid];
        __syncthreads();
        const float4* Pr = (const float4*)(g_P + (size_t)chunk*16384);
        float acc = 0.f;
        #pragma unroll
        for (int j = 0; j < 8; j++) {
            int jj = (j + 2*dq) & 7;
            float4 pv = Pr[tid*8 + jj];
            float4 c4 = *(const float4*)&cv[dq*32 + jj*4];
            acc += pv.x*c4.x + pv.y*c4.y + pv.z*c4.z + pv.w*c4.w;
        }
        acc += __shfl_xor_sync(0xffffffffu, acc, 1);
        acc += __shfl_xor_sync(0xffffffffu, acc, 2);
        if (dq == 0) nv[r] = acc + g_d[chunk*128 + r];
        __syncthreads();
        if (tid < 128) cv[tid] = nv[tid];
        __syncthreads();
    }
}

// ---------------- pass C: within-chunk recurrence ----------------
__global__ __launch_bounds__(512) void passC_kern() {
    int chunk = blockIdx.x;
    int b = chunk >> 5, ci = chunk & 31;
    size_t tokBase = (size_t)b*SS + (size_t)ci*CHL;
    int tid = threadIdx.x;
    int r = tid >> 2, dq = tid & 3;
    __shared__ float cs[2][128];
    if (tid < 128) cs[0][tid] = g_cb[chunk*128 + tid];
    __syncthreads();

    const float4* Ab = (const float4*)(g_A + tokBase*16384);
    float4 buf[8];
    #pragma unroll
    for (int i = 0; i < 8; i++) buf[i] = Ab[tid*8 + ((i + 2*dq) & 7)];

    int p = 0;
    for (int s = 0; s < CHL; s++) {
        float4 nbuf[8];
        if (s + 1 < CHL) {
            const float4* An = Ab + (size_t)(s+1)*4096;
            #pragma unroll
            for (int i = 0; i < 8; i++) nbuf[i] = An[tid*8 + ((i + 2*dq) & 7)];
        }
        float acc = 0.f;
        #pragma unroll
        for (int i = 0; i < 8; i++) {
            int ii = (i + 2*dq) & 7;
            float4 cv = *(const float4*)&cs[p][dq*32 + ii*4];
            acc += buf[i].x*cv.x + buf[i].y*cv.y + buf[i].z*cv.z + buf[i].w*cv.w;
        }
        acc += __shfl_xor_sync(0xffffffffu, acc, 1);
        acc += __shfl_xor_sync(0xffffffffu, acc, 2);
        if (dq == 0) {
            float cn = acc + g_bin[(tokBase + s)*128 + r];
            cs[p ^ 1][r] = cn;
            g_c[(tokBase + s)*128 + r] = cn;
        }
        __syncthreads();
        p ^= 1;
        #pragma unroll
        for (int i = 0; i < 8; i++) buf[i] = nbuf[i];
    }
}

// ---------------- host launcher ----------------
extern "C" void kernel_launch(void* const* d_in, const int* in_sizes, int n_in,
                              void* d_out, int out_size) {
    const float* x   = (const float*)d_in[0];
    const float* Wq  = (const float*)d_in[1];
    const float* bq  = (const float*)d_in[2];
    const float* Wk  = (const float*)d_in[3];
    const float* bk  = (const float*)d_in[4];
    const float* Wv  = (const float*)d_in[5];
    const float* bv  = (const float*)d_in[6];
    const float* Wa  = (const float*)d_in[7];
    const float* ba  = (const float*)d_in[8];
    const float* Wdn = (const float*)d_in[9];
    const float* Wup = (const float*)d_in[10];
    float* out = (float*)d_out;

    float *pA, *pWcat;
    __nv_bfloat16 *pQh, *pQl, *pKh, *pKl, *pAh, *pAl, *pMTh, *pMTl, *pWd2h, *pWd2l, *pWu3h, *pWu3l;
    cudaGetSymbolAddress((void**)&pA,    g_A);
    cudaGetSymbolAddress((void**)&pWcat, g_Wcat);
    cudaGetSymbolAddress((void**)&pQh,   g_qh);
    cudaGetSymbolAddress((void**)&pQl,   g_ql);
    cudaGetSymbolAddress((void**)&pKh,   g_kh);
    cudaGetSymbolAddress((void**)&pKl,   g_kl);
    cudaGetSymbolAddress((void**)&pAh,   g_ah);
    cudaGetSymbolAddress((void**)&pAl,   g_al);
    cudaGetSymbolAddress((void**)&pMTh,  g_MTh);
    cudaGetSymbolAddress((void**)&pMTl,  g_MTl);
    cudaGetSymbolAddress((void**)&pWd2h, g_Wd2h);
    cudaGetSymbolAddress((void**)&pWd2l, g_Wd2l);
    cudaGetSymbolAddress((void**)&pWu3h, g_Wu3h);
    cudaGetSymbolAddress((void**)&pWu3l, g_Wu3l);

    static const int PASSA_SMEM = (128*132 + 2*128*132 + 2*128) * 4;
    cudaFuncSetAttribute(passA_kern, cudaFuncAttributeMaxDynamicSharedMemorySize, PASSA_SMEM);

    const int SM0 = EPI_OFF;                 // 73728
    const int SM1 = EPI_OFF + 128*68*4;      // 108544
    const int SM2 = EPI_OFF + 128*132*4;     // 141312
    cudaFuncSetAttribute(hgemm<0>, cudaFuncAttributeMaxDynamicSharedMemorySize, SM0);
    cudaFuncSetAttribute(hgemm<1>, cudaFuncAttributeMaxDynamicSharedMemorySize, SM1);
    cudaFuncSetAttribute(hgemm<2>, cudaFuncAttributeMaxDynamicSharedMemorySize, SM2);

    // 1. weight prep (bf16 splits)
    prep_all<<<5184, 256>>>(Wq, bq, Wk, bk, Wv, bv, Wa, ba, Wdn, Wup);
    // 2. projection + split/sigmoid/bf16 epilogue
    gemm_proj<<<dim3(2, 64), 256>>>(x, pWcat, NTOK, 256, DMM);
    // 3. bin mma-GEMM (k @ Wd2^T, fused v-contraction -> g_bin)
    hgemm<1><<<dim3(64, 64), 256, SM1>>>(pKh, pKl, pWd2h, pWd2l, nullptr);
    // 4. A mma-GEMM (alpha @ MT^T -> g_A)    <-- ncu capture slot
    hgemm<0><<<dim3(128, 64), 256, SM0>>>(pAh, pAl, pMTh, pMTl, pA);
    // 5. chunk propagators
    passA_kern<<<NCH, 512, PASSA_SMEM>>>();
    // 6. cross-chunk scan
    passB_kern<<<BB, 512>>>();
    // 7. within-chunk recurrence
    passC_kern<<<NCH, 512>>>();
    // 8. o mma-GEMM (q @ Wu3^T, fused c-contraction -> out)
    hgemm<2><<<dim3(64, 64), 256, SM2>>>(pQh, pQl, pWu3h, pWu3l, out);
}

// round 9
// speedup vs baseline: 2.7764x; 1.5726x over previous
#include <cuda_runtime.h>
#include <cuda_bf16.h>
#include <math.h>
#include <stdint.h>

#define BB 4
#define SS 2048
#define DMM 1024
#define NTOK (BB*SS)          /* 8192 */
#define CHL 64
#define NCH (NTOK/CHL)        /* 128 */

// ---------------- scratch ----------------
__device__ float g_Wcat[256*DMM];
__device__ float g_bcat[256];
__device__ float g_v[NTOK*64];
__device__ __nv_bfloat16 g_qh[NTOK*64], g_ql[NTOK*64];
__device__ __nv_bfloat16 g_kh[NTOK*64], g_kl[NTOK*64];
__device__ __nv_bfloat16 g_ah[NTOK*64], g_al[NTOK*64];
__device__ __nv_bfloat16 g_MTh[16384*64], g_MTl[16384*64];   // [(c*128+d)][j]
__device__ __nv_bfloat16 g_Wd2h[8192*64], g_Wd2l[8192*64];   // [(c*64+v)][j]
__device__ __nv_bfloat16 g_Wu3h[8192*64], g_Wu3l[8192*64];   // [(v*128+c)][k]
__device__ float g_bin[NTOK*128];
__device__ float g_A[(size_t)NTOK*16384];                    // 512 MB [t][c*128+d]
__device__ float g_P[(size_t)NCH*16384];                     // Q layout: [chunk][n*128+r] = P^T
__device__ float g_d[NCH*128];
__device__ float g_cb[NCH*128];
__device__ float g_c[NTOK*128];

// ---------------- f32x2 helpers ----------------
__device__ __forceinline__ unsigned long long dupf(float a) {
    unsigned long long r;
    asm("mov.b64 %0, {%1, %1};" : "=l"(r) : "f"(a));
    return r;
}
__device__ __forceinline__ void fma2(unsigned long long& c, unsigned long long a, unsigned long long b) {
    asm("fma.rn.f32x2 %0, %1, %2, %0;" : "+l"(c) : "l"(a), "l"(b));
}
__device__ __forceinline__ void unpk(unsigned long long v, float& lo, float& hi) {
    asm("mov.b64 {%0, %1}, %2;" : "=f"(lo), "=f"(hi) : "l"(v));
}

// ---------------- mma helpers ----------------
__device__ __forceinline__ uint32_t smem_u32(const void* p) {
    uint32_t a;
    asm("{ .reg .u64 t; cvta.to.shared.u64 t, %1; cvt.u32.u64 %0, t; }" : "=r"(a) : "l"(p));
    return a;
}
#define LDSM4(r, addr) \
    asm volatile("ldmatrix.sync.aligned.m8n8.x4.shared.b16 {%0,%1,%2,%3}, [%4];" \
        : "=r"((r)[0]), "=r"((r)[1]), "=r"((r)[2]), "=r"((r)[3]) : "r"(addr))
#define MMA16816(d, a, b0, b1) \
    asm volatile("mma.sync.aligned.m16n8k16.row.col.f32.bf16.bf16.f32 " \
        "{%0,%1,%2,%3}, {%4,%5,%6,%7}, {%8,%9}, {%0,%1,%2,%3};" \
        : "+f"((d)[0]), "+f"((d)[1]), "+f"((d)[2]), "+f"((d)[3]) \
        : "r"((a)[0]), "r"((a)[1]), "r"((a)[2]), "r"((a)[3]), "r"(b0), "r"(b1))
#define CP16(dst, src) \
    asm volatile("cp.async.cg.shared.global [%0], [%1], 16;" :: "r"(dst), "l"(src) : "memory")
#define CP_COMMIT() asm volatile("cp.async.commit_group;" ::: "memory")
#define CP_WAIT0()  asm volatile("cp.async.wait_group 0;" ::: "memory")

__device__ __forceinline__ void split_bf16(float x, __nv_bfloat16& h, __nv_bfloat16& l) {
    h = __float2bfloat16(x);
    l = __float2bfloat16(x - __bfloat162float(h));
}

// ---------------- merged prep: build_M | concat | wd2 | wu3 (bf16-split outputs) ----------------
__global__ __launch_bounds__(256) void prep_all(
        const float* __restrict__ Wq, const float* __restrict__ bq,
        const float* __restrict__ Wk, const float* __restrict__ bk,
        const float* __restrict__ Wv, const float* __restrict__ bv,
        const float* __restrict__ Wa, const float* __restrict__ ba,
        const float* __restrict__ Wd, const float* __restrict__ Wu) {
    __shared__ float sd[128][33];
    __shared__ float su[32][128];
    int bid = blockIdx.x;
    int tid = threadIdx.x;
    if (bid < 64) {
        int j = bid;
        int c0 = tid >> 1;
        int dbase = (tid & 1) * 64;
        float acc[64];
        #pragma unroll
        for (int i = 0; i < 64; i++) acc[i] = 0.f;
        for (int vp = 0; vp < 2; vp++) {
            for (int l = tid; l < 128*32; l += 256) {
                int c = l >> 5, v = l & 31;
                sd[c][v] = Wd[(size_t)c*4096 + j*64 + vp*32 + v];
            }
            for (int l = tid; l < 32*128; l += 256) {
                int v = l >> 7, d = l & 127;
                su[v][d] = Wu[(size_t)(j*64 + vp*32 + v)*128 + d];
            }
            __syncthreads();
            #pragma unroll 8
            for (int v = 0; v < 32; v++) {
                float a = sd[c0][v];
                #pragma unroll
                for (int d = 0; d < 64; d++)
                    acc[d] += a * su[v][dbase + d];
            }
            __syncthreads();
        }
        for (int d = 0; d < 64; d++) {
            __nv_bfloat16 h, l;
            split_bf16(acc[d], h, l);
            size_t pos = (size_t)(c0*128 + dbase + d)*64 + j;
            g_MTh[pos] = h; g_MTl[pos] = l;
        }
    } else if (bid < 1088) {
        int idx = (bid - 64)*256 + tid;
        int r = idx >> 10, cc = idx & 1023;
        float w;
        if (r < 64)       w = Wq[r*DMM + cc];
        else if (r < 128) w = Wk[(r-64)*DMM + cc];
        else if (r < 192) w = Wv[(r-128)*DMM + cc];
        else              w = Wa[(r-192)*DMM + cc];
        g_Wcat[idx] = w;
        if (bid == 64) {
            g_bcat[tid] = (tid < 64) ? bq[tid] :
                          (tid < 128) ? bk[tid-64] :
                          (tid < 192) ? bv[tid-128] : ba[tid-192];
        }
    } else if (bid < 3136) {
        int idx = (bid - 1088)*256 + tid;       // over 128*4096
        int c = idx >> 12, rest = idx & 4095;
        int j = rest >> 6, v = rest & 63;
        __nv_bfloat16 h, l;
        split_bf16(Wd[idx], h, l);
        size_t pos = (size_t)((c<<6) + v)*64 + j;
        g_Wd2h[pos] = h; g_Wd2l[pos] = l;
    } else {
        int idx = (bid - 3136)*256 + tid;       // over 4096*128
        int kv = idx >> 7, c = idx & 127;
        int k = kv >> 6, v = kv & 63;
        __nv_bfloat16 h, l;
        split_bf16(Wu[idx], h, l);
        size_t pos = (size_t)(v*128 + c)*64 + k;
        g_Wu3h[pos] = h; g_Wu3l[pos] = l;
    }
}

// ---------------- projection GEMM (K=1024), split/sigmoid/bf16 epilogue ----------------
__global__ void __launch_bounds__(256) gemm_proj(const float* __restrict__ A,
                                                 const float* __restrict__ B,
                                                 int M, int N, int K) {
    __shared__ __align__(16) float As[2][16][132];
    __shared__ __align__(16) float Bs[2][16][132];
    int tid = threadIdx.x;
    int tx = tid & 15, ty = tid >> 4;
    int row0 = blockIdx.y*128, col0 = blockIdx.x*128;
    int lr = tid >> 1;
    int lk = (tid & 1) * 8;
    const float* Ap = A + (size_t)(row0+lr)*K + lk;
    const float* Bp = B + (size_t)(col0+lr)*K + lk;

    unsigned long long acc[8][4];
    #pragma unroll
    for (int i = 0; i < 8; i++)
        #pragma unroll
        for (int j = 0; j < 4; j++) acc[i][j] = 0ULL;

    int nt = K >> 4;
    {
        float4 a0 = *(const float4*)(Ap + 0);
        float4 a1 = *(const float4*)(Ap + 4);
        float4 b0 = *(const float4*)(Bp + 0);
        float4 b1 = *(const float4*)(Bp + 4);
        As[0][lk+0][lr]=a0.x; As[0][lk+1][lr]=a0.y; As[0][lk+2][lr]=a0.z; As[0][lk+3][lr]=a0.w;
        As[0][lk+4][lr]=a1.x; As[0][lk+5][lr]=a1.y; As[0][lk+6][lr]=a1.z; As[0][lk+7][lr]=a1.w;
        Bs[0][lk+0][lr]=b0.x; Bs[0][lk+1][lr]=b0.y; Bs[0][lk+2][lr]=b0.z; Bs[0][lk+3][lr]=b0.w;
        Bs[0][lk+4][lr]=b1.x; Bs[0][lk+5][lr]=b1.y; Bs[0][lk+6][lr]=b1.z; Bs[0][lk+7][lr]=b1.w;
    }
    __syncthreads();

    #pragma unroll 1
    for (int t = 0; t < nt; t++) {
        int cur = t & 1;
        float4 a0, a1, b0, b1;
        if (t + 1 < nt) {
            int k0 = (t+1) << 4;
            a0 = *(const float4*)(Ap + k0);
            a1 = *(const float4*)(Ap + k0 + 4);
            b0 = *(const float4*)(Bp + k0);
            b1 = *(const float4*)(Bp + k0 + 4);
        }
        #pragma unroll
        for (int kk = 0; kk < 16; kk++) {
            float4 af0 = *(const float4*)&As[cur][kk][ty*8];
            float4 af1 = *(const float4*)&As[cur][kk][ty*8 + 4];
            ulonglong2 bv0 = *(const ulonglong2*)&Bs[cur][kk][tx*8];
            ulonglong2 bv1 = *(const ulonglong2*)&Bs[cur][kk][tx*8 + 4];
            float av[8] = {af0.x, af0.y, af0.z, af0.w, af1.x, af1.y, af1.z, af1.w};
            unsigned long long bw[4] = {bv0.x, bv0.y, bv1.x, bv1.y};
            #pragma unroll
            for (int i = 0; i < 8; i++) {
                unsigned long long ad = dupf(av[i]);
                #pragma unroll
                for (int j = 0; j < 4; j++) fma2(acc[i][j], ad, bw[j]);
            }
        }
        if (t + 1 < nt) {
            int nb = cur ^ 1;
            As[nb][lk+0][lr]=a0.x; As[nb][lk+1][lr]=a0.y; As[nb][lk+2][lr]=a0.z; As[nb][lk+3][lr]=a0.w;
            As[nb][lk+4][lr]=a1.x; As[nb][lk+5][lr]=a1.y; As[nb][lk+6][lr]=a1.z; As[nb][lk+7][lr]=a1.w;
            Bs[nb][lk+0][lr]=b0.x; Bs[nb][lk+1][lr]=b0.y; Bs[nb][lk+2][lr]=b0.z; Bs[nb][lk+3][lr]=b0.w;
            Bs[nb][lk+4][lr]=b1.x; Bs[nb][lk+5][lr]=b1.y; Bs[nb][lk+6][lr]=b1.z; Bs[nb][lk+7][lr]=b1.w;
        }
        __syncthreads();
    }

    #pragma unroll
    for (int i = 0; i < 8; i++) {
        int m = row0 + ty*8 + i;
        float val[8];
        unpk(acc[i][0], val[0], val[1]); unpk(acc[i][1], val[2], val[3]);
        unpk(acc[i][2], val[4], val[5]); unpk(acc[i][3], val[6], val[7]);
        int n0 = col0 + tx*8;
        const float* bp = g_bcat + n0;
        #pragma unroll
        for (int e = 0; e < 8; e++) val[e] += bp[e];
        int blk = n0 >> 6;
        int w = n0 & 63;
        if (blk == 2) {
            *(float4*)(g_v + (size_t)m*64 + w)     = *(float4*)&val[0];
            *(float4*)(g_v + (size_t)m*64 + w + 4) = *(float4*)&val[4];
        } else {
            __nv_bfloat16* bh;
            __nv_bfloat16* bl;
            if (blk == 0)      { bh = g_qh; bl = g_ql; }
            else if (blk == 1) { bh = g_kh; bl = g_kl; }
            else               { bh = g_ah; bl = g_al;
                #pragma unroll
                for (int e = 0; e < 8; e++) val[e] = 1.f/(1.f+expf(-val[e]));
            }
            __nv_bfloat16 h8[8], l8[8];
            #pragma unroll
            for (int e = 0; e < 8; e++) split_bf16(val[e], h8[e], l8[e]);
            *(uint4*)(bh + (size_t)m*64 + w) = *(uint4*)h8;
            *(uint4*)(bl + (size_t)m*64 + w) = *(uint4*)l8;
        }
    }
}

// ---------------- mma.sync bf16-split K=64 GEMM, 128x128 tile, 256 threads ----------------
#define TILEB 18432              /* 128 rows * 144 B */
#define EPI_OFF (4*TILEB)        /* 73728 */
template<int MODE>
__global__ void __launch_bounds__(256) hgemm(const __nv_bfloat16* __restrict__ Ah,
                                             const __nv_bfloat16* __restrict__ Al,
                                             const __nv_bfloat16* __restrict__ Bh,
                                             const __nv_bfloat16* __restrict__ Bl,
                                             float* __restrict__ C) {
    extern __shared__ __align__(16) char smem[];
    uint32_t sb = smem_u32(smem);
    int tid = threadIdx.x;
    int lane = tid & 31, wid = tid >> 5;
    int gid = lane >> 2, tig = lane & 3;
    int warpM = wid >> 2, warpN = wid & 3;
    int m0 = warpM*64, n0 = warpN*32;
    int row0 = blockIdx.y*128, col0 = blockIdx.x*128;

    {
        const uint4* srcs[4] = {
            (const uint4*)(Ah + (size_t)row0*64), (const uint4*)(Al + (size_t)row0*64),
            (const uint4*)(Bh + (size_t)col0*64), (const uint4*)(Bl + (size_t)col0*64) };
        #pragma unroll
        for (int t = 0; t < 4; t++) {
            char* dst = smem + t*TILEB;
            #pragma unroll
            for (int j = 0; j < 4; j++) {
                int idx = tid + j*256;
                int r = idx >> 3, ch = idx & 7;
                *(uint4*)(dst + r*144 + ch*16) = srcs[t][idx];
            }
        }
    }
    if (MODE == 1) {
        float* sv = (float*)(smem + EPI_OFF);
        const float4* vp = (const float4*)(g_v + (size_t)row0*64);
        #pragma unroll
        for (int j = 0; j < 8; j++) {
            int idx = tid + j*256;
            int r = idx >> 4, q = idx & 15;
            *(float4*)&sv[r*68 + q*4] = vp[idx];
        }
    }
    if (MODE == 2) {
        float* sc = (float*)(smem + EPI_OFF);
        const float4* cp = (const float4*)(g_c + (size_t)row0*128);
        #pragma unroll
        for (int j = 0; j < 16; j++) {
            int idx = tid + j*256;
            int r = idx >> 5, q = idx & 31;
            *(float4*)&sc[r*132 + q*4] = cp[idx];
        }
    }
    __syncthreads();

    int q8 = lane >> 3, i8 = lane & 7;
    uint32_t aLane = (uint32_t)(((q8 & 1)*8 + i8)*144 + (q8 >> 1)*16);
    uint32_t bLane = (uint32_t)(((q8 >> 1)*8 + i8)*144 + (q8 & 1)*16);

    float d[4][4][4];
    #pragma unroll
    for (int mt = 0; mt < 4; mt++)
        #pragma unroll
        for (int nt = 0; nt < 4; nt++)
            #pragma unroll
            for (int e = 0; e < 4; e++) d[mt][nt][e] = 0.f;

    #pragma unroll
    for (int term = 0; term < 3; term++) {
        uint32_t aBase = sb + (term == 2 ? TILEB : 0) + (uint32_t)m0*144 + aLane;
        uint32_t bBase = sb + 2*TILEB + (term == 1 ? TILEB : 0) + (uint32_t)n0*144 + bLane;
        #pragma unroll
        for (int ks = 0; ks < 4; ks++) {
            uint32_t koff = (uint32_t)(ks*32);
            uint32_t af[4][4], bf2[2][4];
            #pragma unroll
            for (int mt = 0; mt < 4; mt++)
                LDSM4(af[mt], aBase + mt*16*144 + koff);
            #pragma unroll
            for (int nt2 = 0; nt2 < 2; nt2++)
                LDSM4(bf2[nt2], bBase + nt2*16*144 + koff);
            #pragma unroll
            for (int mt = 0; mt < 4; mt++)
                #pragma unroll
                for (int nt = 0; nt < 4; nt++)
                    MMA16816(d[mt][nt], af[mt], bf2[nt>>1][(nt&1)*2], bf2[nt>>1][(nt&1)*2+1]);
        }
    }
    __syncthreads();

    if (MODE == 0) {
        float* Ds = (float*)smem;
        #pragma unroll
        for (int mt = 0; mt < 4; mt++) {
            int r0 = m0 + mt*16 + gid, r1 = r0 + 8;
            #pragma unroll
            for (int nt = 0; nt < 4; nt++) {
                int cl = n0 + nt*8 + tig*2;
                *(float2*)&Ds[r0*132 + cl] = make_float2(d[mt][nt][0], d[mt][nt][1]);
                *(float2*)&Ds[r1*132 + cl] = make_float2(d[mt][nt][2], d[mt][nt][3]);
            }
        }
        __syncthreads();
        #pragma unroll
        for (int it = 0; it < 16; it++) {
            int idx = tid + it*256;
            int r = idx >> 5, q4 = idx & 31;
            *(float4*)(C + (size_t)(row0 + r)*16384 + col0 + q4*4) =
                *(const float4*)&Ds[r*132 + q4*4];
        }
    } else if (MODE == 1) {
        const float* sv = (const float*)(smem + EPI_OFF);
        float* red = (float*)smem;
        #pragma unroll
        for (int mt = 0; mt < 4; mt++) {
            int r0 = m0 + mt*16 + gid, r1 = r0 + 8;
            float p0 = 0.f, p1 = 0.f;
            #pragma unroll
            for (int nt = 0; nt < 4; nt++) {
                int v = (n0 + nt*8 + tig*2) & 63;
                p0 += d[mt][nt][0]*sv[r0*68 + v] + d[mt][nt][1]*sv[r0*68 + v + 1];
                p1 += d[mt][nt][2]*sv[r1*68 + v] + d[mt][nt][3]*sv[r1*68 + v + 1];
            }
            p0 += __shfl_xor_sync(0xffffffffu, p0, 1);
            p0 += __shfl_xor_sync(0xffffffffu, p0, 2);
            p1 += __shfl_xor_sync(0xffffffffu, p1, 1);
            p1 += __shfl_xor_sync(0xffffffffu, p1, 2);
            if (tig == 0) { red[r0*4 + warpN] = p0; red[r1*4 + warpN] = p1; }
        }
        __syncthreads();
        if (tid < 128) {
            int cb = blockIdx.x*2;
            float s0 = red[tid*4 + 0] + red[tid*4 + 1];
            float s1 = red[tid*4 + 2] + red[tid*4 + 3];
            g_bin[(size_t)(row0 + tid)*128 + cb]     = s0;
            g_bin[(size_t)(row0 + tid)*128 + cb + 1] = s1;
        }
    } else {
        const float* sc = (const float*)(smem + EPI_OFF);
        float* red = (float*)smem;
        #pragma unroll
        for (int mt = 0; mt < 4; mt++) {
            int r0 = m0 + mt*16 + gid, r1 = r0 + 8;
            float p0 = 0.f, p1 = 0.f;
            #pragma unroll
            for (int nt = 0; nt < 4; nt++) {
                int c = n0 + nt*8 + tig*2;
                p0 += d[mt][nt][0]*sc[r0*132 + c] + d[mt][nt][1]*sc[r0*132 + c + 1];
                p1 += d[mt][nt][2]*sc[r1*132 + c] + d[mt][nt][3]*sc[r1*132 + c + 1];
            }
            p0 += __shfl_xor_sync(0xffffffffu, p0, 1);
            p0 += __shfl_xor_sync(0xffffffffu, p0, 2);
            p1 += __shfl_xor_sync(0xffffffffu, p1, 1);
            p1 += __shfl_xor_sync(0xffffffffu, p1, 2);
            if (tig == 0) { red[r0*4 + warpN] = p0; red[r1*4 + warpN] = p1; }
        }
        __syncthreads();
        if (tid < 128) {
            float s = red[tid*4+0] + red[tid*4+1] + red[tid*4+2] + red[tid*4+3];
            C[(size_t)(row0 + tid)*64 + blockIdx.x] = s;
        }
    }
}

// ---------------- pass A (mma.sync): per-chunk propagator Q = P^T, offset d ----------------
// Q_{s} = Q_{s-1} @ A_s^T, Q_{-1} = I, computed 3-term bf16-split on tensor cores.
// d_s = A_s d_{s-1} + bin_s computed fp32 from the staging buffer.
// smem layout (bytes):
#define PA_QH  0         /* bf16 [128][136] = 34816 */
#define PA_QL  34816
#define PA_AH  69632
#define PA_AL  104448
#define PA_STG 139264    /* fp32 [16384] = 65536 */
#define PA_DS  204800    /* fp32 [2][128] = 1024 */
#define PA_SMEM 205824
__global__ __launch_bounds__(512) void passA_mma() {
    extern __shared__ __align__(16) char sm[];
    uint32_t sb = smem_u32(sm);
    __nv_bfloat16* sQh = (__nv_bfloat16*)(sm + PA_QH);
    __nv_bfloat16* sQl = (__nv_bfloat16*)(sm + PA_QL);
    __nv_bfloat16* sAh = (__nv_bfloat16*)(sm + PA_AH);
    __nv_bfloat16* sAl = (__nv_bfloat16*)(sm + PA_AL);
    float* stage = (float*)(sm + PA_STG);
    float* ds = (float*)(sm + PA_DS);

    int tid = threadIdx.x;
    int lane = tid & 31, wid = tid >> 5;
    int gid = lane >> 2, tig = lane & 3;
    int wm = wid >> 2, wn = wid & 3;
    int chunk = blockIdx.x;
    int b = chunk >> 5, ci = chunk & 31;
    size_t tokBase = (size_t)b*SS + (size_t)ci*CHL;

    // init Q = I, ds = 0
    for (int idx = tid; idx < 128*136; idx += 512) {
        int r = idx / 136, k = idx - r*136;
        sQh[idx] = __float2bfloat16(r == k ? 1.f : 0.f);
        sQl[idx] = __float2bfloat16(0.f);
    }
    if (tid < 256) ds[tid] = 0.f;

    // prologue: stage A(0)
    {
        const float4* src = (const float4*)(g_A + tokBase*16384);
        #pragma unroll
        for (int j = 0; j < 8; j++) {
            int idx = tid + j*512;
            CP16(sb + PA_STG + idx*16, src + idx);
        }
        CP_COMMIT(); CP_WAIT0();
    }
    __syncthreads();

    int q8 = lane >> 3, i8 = lane & 7;
    uint32_t aLane = (uint32_t)(((q8 & 1)*8 + i8)*272 + (q8 >> 1)*16);
    uint32_t bLane = (uint32_t)(((q8 >> 1)*8 + i8)*272 + (q8 & 1)*16);
    uint32_t qhB = sb + PA_QH + (uint32_t)(wm*32)*272 + aLane;
    uint32_t qlB = sb + PA_QL + (uint32_t)(wm*32)*272 + aLane;
    uint32_t ahB = sb + PA_AH + (uint32_t)(wn*32)*272 + bLane;
    uint32_t alB = sb + PA_AL + (uint32_t)(wn*32)*272 + bLane;

    int dr = tid >> 2, dq = tid & 3;
    int cur = 0;
    for (int s = 0; s < CHL; s++) {
        // 1. convert staged A(s) -> bf16 split tiles; fp32 d-update from stage
        #pragma unroll
        for (int i = 0; i < 16; i++) {
            int idx = tid + i*512;               // over 8192 float2
            float2 x = *(const float2*)&stage[idx*2];
            int r = idx >> 6, k = (idx & 63)*2;
            __nv_bfloat16 hp[2], lp[2];
            split_bf16(x.x, hp[0], lp[0]);
            split_bf16(x.y, hp[1], lp[1]);
            *(uint32_t*)&sAh[r*136 + k] = *(uint32_t*)hp;
            *(uint32_t*)&sAl[r*136 + k] = *(uint32_t*)lp;
        }
        {
            const float* dc = ds + cur*128;
            float dacc = 0.f;
            #pragma unroll
            for (int kk = 0; kk < 32; kk++) {
                int k = dq*32 + ((kk + lane) & 31);
                dacc += stage[dr*128 + k] * dc[k];
            }
            dacc += __shfl_xor_sync(0xffffffffu, dacc, 1);
            dacc += __shfl_xor_sync(0xffffffffu, dacc, 2);
            if (dq == 0)
                ds[(cur^1)*128 + dr] = dacc + g_bin[(tokBase + s)*128 + dr];
        }
        __syncthreads();
        // 2. prefetch next A into stage (overlaps mma)
        if (s + 1 < CHL) {
            const float4* src = (const float4*)(g_A + (tokBase + s + 1)*16384);
            #pragma unroll
            for (int j = 0; j < 8; j++) {
                int idx = tid + j*512;
                CP16(sb + PA_STG + idx*16, src + idx);
            }
            CP_COMMIT();
        }
        // 3. newQ = Q @ A^T, 3-term bf16-split
        float acc[2][4][4];
        #pragma unroll
        for (int mt = 0; mt < 2; mt++)
            #pragma unroll
            for (int nt = 0; nt < 4; nt++)
                #pragma unroll
                for (int e = 0; e < 4; e++) acc[mt][nt][e] = 0.f;
        #pragma unroll
        for (int ks = 0; ks < 8; ks++) {
            uint32_t ko = (uint32_t)(ks*32);
            uint32_t qh[2][4], ql[2][4], ah[2][4], al[2][4];
            #pragma unroll
            for (int mt = 0; mt < 2; mt++) {
                LDSM4(qh[mt], qhB + mt*16*272 + ko);
                LDSM4(ql[mt], qlB + mt*16*272 + ko);
            }
            #pragma unroll
            for (int nb = 0; nb < 2; nb++) {
                LDSM4(ah[nb], ahB + nb*16*272 + ko);
                LDSM4(al[nb], alB + nb*16*272 + ko);
            }
            #pragma unroll
            for (int mt = 0; mt < 2; mt++)
                #pragma unroll
                for (int nt = 0; nt < 4; nt++) {
                    int nb = nt >> 1, hh = (nt & 1)*2;
                    MMA16816(acc[mt][nt], qh[mt], ah[nb][hh], ah[nb][hh+1]);
                    MMA16816(acc[mt][nt], qh[mt], al[nb][hh], al[nb][hh+1]);
                    MMA16816(acc[mt][nt], ql[mt], ah[nb][hh], ah[nb][hh+1]);
                }
        }
        __syncthreads();   // all Q reads complete
        // 4. write back newQ (bf16 split) or final fp32 output
        if (s + 1 < CHL) {
            #pragma unroll
            for (int mt = 0; mt < 2; mt++)
                #pragma unroll
                for (int nt = 0; nt < 4; nt++) {
                    int r0 = wm*32 + mt*16 + gid, r1 = r0 + 8;
                    int col = wn*32 + nt*8 + tig*2;
                    __nv_bfloat16 hp[2], lp[2];
                    split_bf16(acc[mt][nt][0], hp[0], lp[0]);
                    split_bf16(acc[mt][nt][1], hp[1], lp[1]);
                    *(uint32_t*)&sQh[r0*136 + col] = *(uint32_t*)hp;
                    *(uint32_t*)&sQl[r0*136 + col] = *(uint32_t*)lp;
                    split_bf16(acc[mt][nt][2], hp[0], lp[0]);
                    split_bf16(acc[mt][nt][3], hp[1], lp[1]);
                    *(uint32_t*)&sQh[r1*136 + col] = *(uint32_t*)hp;
                    *(uint32_t*)&sQl[r1*136 + col] = *(uint32_t*)lp;
                }
        } else {
            #pragma unroll
            for (int mt = 0; mt < 2; mt++)
                #pragma unroll
                for (int nt = 0; nt < 4; nt++) {
                    int r0 = wm*32 + mt*16 + gid, r1 = r0 + 8;
                    int col = wn*32 + nt*8 + tig*2;
                    *(float2*)&stage[r0*128 + col] = make_float2(acc[mt][nt][0], acc[mt][nt][1]);
                    *(float2*)&stage[r1*128 + col] = make_float2(acc[mt][nt][2], acc[mt][nt][3]);
                }
        }
        CP_WAIT0();
        __syncthreads();
        cur ^= 1;
    }
    // output: Q (= P^T) fp32 and final d
    #pragma unroll
    for (int i = 0; i < 32; i++) {
        int idx = tid + i*512;
        g_P[(size_t)chunk*16384 + idx] = stage[idx];
    }
    if (tid < 128) g_d[chunk*128 + tid] = ds[cur*128 + tid];
}

// ---------------- pass B: cross-chunk scan (reads Q = P^T layout) ----------------
__global__ __launch_bounds__(512) void passB_kern() {
    int b = blockIdx.x;
    int tid = threadIdx.x;
    __shared__ float cv[128], nv[128], red[512];
    if (tid < 128) cv[tid] = 0.f;
    __syncthreads();
    int g = tid >> 7, r = tid & 127;
    for (int i = 0; i < SS/CHL; i++) {
        int chunk = b*(SS/CHL) + i;
        if (tid < 128) g_cb[chunk*128 + tid] = cv[tid];
        __syncthreads();
        const float* Q = g_P + (size_t)chunk*16384;
        float acc = 0.f;
        #pragma unroll 8
        for (int kk = 0; kk < 32; kk++) {
            int k = g*32 + kk;
            acc += Q[k*128 + r] * cv[k];     // P[r][k] = Q[k][r]
        }
        red[g*128 + r] = acc;
        __syncthreads();
        if (tid < 128)
            nv[tid] = red[tid] + red[128+tid] + red[256+tid] + red[384+tid]
                    + g_d[chunk*128 + tid];
        __syncthreads();
        if (tid < 128) cv[tid] = nv[tid];
        __syncthreads();
    }
}

// ---------------- pass C: within-chunk recurrence ----------------
__global__ __launch_bounds__(512) void passC_kern() {
    int chunk = blockIdx.x;
    int b = chunk >> 5, ci = chunk & 31;
    size_t tokBase = (size_t)b*SS + (size_t)ci*CHL;
    int tid = threadIdx.x;
    int r = tid >> 2, dq = tid & 3;
    __shared__ float cs[2][128];
    if (tid < 128) cs[0][tid] = g_cb[chunk*128 + tid];
    __syncthreads();

    const float4* Ab = (const float4*)(g_A + tokBase*16384);
    float4 buf[8];
    #pragma unroll
    for (int i = 0; i < 8; i++) buf[i] = Ab[tid*8 + ((i + 2*dq) & 7)];

    int p = 0;
    for (int s = 0; s < CHL; s++) {
        float4 nbuf[8];
        if (s + 1 < CHL) {
            const float4* An = Ab + (size_t)(s+1)*4096;
            #pragma unroll
            for (int i = 0; i < 8; i++) nbuf[i] = An[tid*8 + ((i + 2*dq) & 7)];
        }
        float acc = 0.f;
        #pragma unroll
        for (int i = 0; i < 8; i++) {
            int ii = (i + 2*dq) & 7;
            float4 cv = *(const float4*)&cs[p][dq*32 + ii*4];
            acc += buf[i].x*cv.x + buf[i].y*cv.y + buf[i].z*cv.z + buf[i].w*cv.w;
        }
        acc += __shfl_xor_sync(0xffffffffu, acc, 1);
        acc += __shfl_xor_sync(0xffffffffu, acc, 2);
        if (dq == 0) {
            float cn = acc + g_bin[(tokBase + s)*128 + r];
            cs[p ^ 1][r] = cn;
            g_c[(tokBase + s)*128 + r] = cn;
        }
        __syncthreads();
        p ^= 1;
        #pragma unroll
        for (int i = 0; i < 8; i++) buf[i] = nbuf[i];
    }
}

// ---------------- host launcher ----------------
extern "C" void kernel_launch(void* const* d_in, const int* in_sizes, int n_in,
                              void* d_out, int out_size) {
    const float* x   = (const float*)d_in[0];
    const float* Wq  = (const float*)d_in[1];
    const float* bq  = (const float*)d_in[2];
    const float* Wk  = (const float*)d_in[3];
    const float* bk  = (const float*)d_in[4];
    const float* Wv  = (const float*)d_in[5];
    const float* bv  = (const float*)d_in[6];
    const float* Wa  = (const float*)d_in[7];
    const float* ba  = (const float*)d_in[8];
    const float* Wdn = (const float*)d_in[9];
    const float* Wup = (const float*)d_in[10];
    float* out = (float*)d_out;

    float *pA, *pWcat;
    __nv_bfloat16 *pQh, *pQl, *pKh, *pKl, *pAh, *pAl, *pMTh, *pMTl, *pWd2h, *pWd2l, *pWu3h, *pWu3l;
    cudaGetSymbolAddress((void**)&pA,    g_A);
    cudaGetSymbolAddress((void**)&pWcat, g_Wcat);
    cudaGetSymbolAddress((void**)&pQh,   g_qh);
    cudaGetSymbolAddress((void**)&pQl,   g_ql);
    cudaGetSymbolAddress((void**)&pKh,   g_kh);
    cudaGetSymbolAddress((void**)&pKl,   g_kl);
    cudaGetSymbolAddress((void**)&pAh,   g_ah);
    cudaGetSymbolAddress((void**)&pAl,   g_al);
    cudaGetSymbolAddress((void**)&pMTh,  g_MTh);
    cudaGetSymbolAddress((void**)&pMTl,  g_MTl);
    cudaGetSymbolAddress((void**)&pWd2h, g_Wd2h);
    cudaGetSymbolAddress((void**)&pWd2l, g_Wd2l);
    cudaGetSymbolAddress((void**)&pWu3h, g_Wu3h);
    cudaGetSymbolAddress((void**)&pWu3l, g_Wu3l);

    cudaFuncSetAttribute(passA_mma, cudaFuncAttributeMaxDynamicSharedMemorySize, PA_SMEM);

    const int SM0 = EPI_OFF;                 // 73728
    const int SM1 = EPI_OFF + 128*68*4;      // 108544
    const int SM2 = EPI_OFF + 128*132*4;     // 141312
    cudaFuncSetAttribute(hgemm<0>, cudaFuncAttributeMaxDynamicSharedMemorySize, SM0);
    cudaFuncSetAttribute(hgemm<1>, cudaFuncAttributeMaxDynamicSharedMemorySize, SM1);
    cudaFuncSetAttribute(hgemm<2>, cudaFuncAttributeMaxDynamicSharedMemorySize, SM2);

    // 1. weight prep (bf16 splits)
    prep_all<<<5184, 256>>>(Wq, bq, Wk, bk, Wv, bv, Wa, ba, Wdn, Wup);
    // 2. projection + split/sigmoid/bf16 epilogue
    gemm_proj<<<dim3(2, 64), 256>>>(x, pWcat, NTOK, 256, DMM);
    // 3. bin mma-GEMM (k @ Wd2^T, fused v-contraction -> g_bin)
    hgemm<1><<<dim3(64, 64), 256, SM1>>>(pKh, pKl, pWd2h, pWd2l, nullptr);
    // 4. A mma-GEMM (alpha @ MT^T -> g_A)    <-- ncu capture slot
    hgemm<0><<<dim3(128, 64), 256, SM0>>>(pAh, pAl, pMTh, pMTl, pA);
    // 5. chunk propagators (tensor cores)
    passA_mma<<<NCH, 512, PA_SMEM>>>();
    // 6. cross-chunk scan
    passB_kern<<<BB, 512>>>();
    // 7. within-chunk recurrence
    passC_kern<<<NCH, 512>>>();
    // 8. o mma-GEMM (q @ Wu3^T, fused c-contraction -> out)
    hgemm<2><<<dim3(64, 64), 256, SM2>>>(pQh, pQl, pWu3h, pWu3l, out);
}

// round 12
// speedup vs baseline: 2.7809x; 1.0016x over previous
#include <cuda_runtime.h>
#include <cuda_bf16.h>
#include <math.h>
#include <stdint.h>

// R10 retry #2 — hardened: unconditional cp.async drain at loop tail,
// prologue staging via plain ld/st. Logic otherwise identical.

#define BB 4
#define SS 2048
#define DMM 1024
#define NTOK (BB*SS)          /* 8192 */
#define CHL 64
#define NCH (NTOK/CHL)        /* 128 */

// ---------------- scratch ----------------
__device__ float g_Wcat[256*DMM];
__device__ float g_bcat[256];
__device__ float g_v[NTOK*64];
__device__ __nv_bfloat16 g_qh[NTOK*64], g_ql[NTOK*64];
__device__ __nv_bfloat16 g_kh[NTOK*64], g_kl[NTOK*64];
__device__ __nv_bfloat16 g_ah[NTOK*64], g_al[NTOK*64];
__device__ __nv_bfloat16 g_MTh[16384*64], g_MTl[16384*64];   // [(c*128+d)][j]
__device__ __nv_bfloat16 g_Wd2h[8192*64], g_Wd2l[8192*64];   // [(c*64+v)][j]
__device__ __nv_bfloat16 g_Wu3h[8192*64], g_Wu3l[8192*64];   // [(v*128+c)][k]
__device__ float g_bin[NTOK*128];
__device__ __nv_bfloat16 g_Ah[(size_t)NTOK*16384];           // 256 MB [t][c*128+d] hi
__device__ __nv_bfloat16 g_Al[(size_t)NTOK*16384];           // 256 MB lo
__device__ float g_P[(size_t)NCH*16384];                     // Q layout: [chunk][n*128+r] = P^T
__device__ float g_d[NCH*128];
__device__ float g_cb[NCH*128];
__device__ float g_c[NTOK*128];

// ---------------- f32x2 helpers ----------------
__device__ __forceinline__ unsigned long long dupf(float a) {
    unsigned long long r;
    asm("mov.b64 %0, {%1, %1};" : "=l"(r) : "f"(a));
    return r;
}
__device__ __forceinline__ void fma2(unsigned long long& c, unsigned long long a, unsigned long long b) {
    asm("fma.rn.f32x2 %0, %1, %2, %0;" : "+l"(c) : "l"(a), "l"(b));
}
__device__ __forceinline__ void unpk(unsigned long long v, float& lo, float& hi) {
    asm("mov.b64 {%0, %1}, %2;" : "=f"(lo), "=f"(hi) : "l"(v));
}

// ---------------- mma helpers ----------------
__device__ __forceinline__ uint32_t smem_u32(const void* p) {
    uint32_t a;
    asm("{ .reg .u64 t; cvta.to.shared.u64 t, %1; cvt.u32.u64 %0, t; }" : "=r"(a) : "l"(p));
    return a;
}
#define LDSM4(r, addr) \
    asm volatile("ldmatrix.sync.aligned.m8n8.x4.shared.b16 {%0,%1,%2,%3}, [%4];" \
        : "=r"((r)[0]), "=r"((r)[1]), "=r"((r)[2]), "=r"((r)[3]) : "r"(addr))
#define MMA16816(d, a, b0, b1) \
    asm volatile("mma.sync.aligned.m16n8k16.row.col.f32.bf16.bf16.f32 " \
        "{%0,%1,%2,%3}, {%4,%5,%6,%7}, {%8,%9}, {%0,%1,%2,%3};" \
        : "+f"((d)[0]), "+f"((d)[1]), "+f"((d)[2]), "+f"((d)[3]) \
        : "r"((a)[0]), "r"((a)[1]), "r"((a)[2]), "r"((a)[3]), "r"(b0), "r"(b1))
#define CP16(dst, src) \
    asm volatile("cp.async.cg.shared.global [%0], [%1], 16;" :: "r"(dst), "l"(src) : "memory")
#define CP_COMMIT() asm volatile("cp.async.commit_group;" ::: "memory")
#define CP_WAIT0()  asm volatile("cp.async.wait_all;" ::: "memory")

__device__ __forceinline__ void split_bf16(float x, __nv_bfloat16& h, __nv_bfloat16& l) {
    h = __float2bfloat16(x);
    l = __float2bfloat16(x - __bfloat162float(h));
}

// ---------------- merged prep ----------------
__global__ __launch_bounds__(256) void prep_all(
        const float* __restrict__ Wq, const float* __restrict__ bq,
        const float* __restrict__ Wk, const float* __restrict__ bk,
        const float* __restrict__ Wv, const float* __restrict__ bv,
        const float* __restrict__ Wa, const float* __restrict__ ba,
        const float* __restrict__ Wd, const float* __restrict__ Wu) {
    __shared__ float sd[128][33];
    __shared__ float su[32][128];
    int bid = blockIdx.x;
    int tid = threadIdx.x;
    if (bid < 64) {
        int j = bid;
        int c0 = tid >> 1;
        int dbase = (tid & 1) * 64;
        float acc[64];
        #pragma unroll
        for (int i = 0; i < 64; i++) acc[i] = 0.f;
        for (int vp = 0; vp < 2; vp++) {
            for (int l = tid; l < 128*32; l += 256) {
                int c = l >> 5, v = l & 31;
                sd[c][v] = Wd[(size_t)c*4096 + j*64 + vp*32 + v];
            }
            for (int l = tid; l < 32*128; l += 256) {
                int v = l >> 7, d = l & 127;
                su[v][d] = Wu[(size_t)(j*64 + vp*32 + v)*128 + d];
            }
            __syncthreads();
            #pragma unroll 8
            for (int v = 0; v < 32; v++) {
                float a = sd[c0][v];
                #pragma unroll
                for (int d = 0; d < 64; d++)
                    acc[d] += a * su[v][dbase + d];
            }
            __syncthreads();
        }
        for (int d = 0; d < 64; d++) {
            __nv_bfloat16 h, l;
            split_bf16(acc[d], h, l);
            size_t pos = (size_t)(c0*128 + dbase + d)*64 + j;
            g_MTh[pos] = h; g_MTl[pos] = l;
        }
    } else if (bid < 1088) {
        int idx = (bid - 64)*256 + tid;
        int r = idx >> 10, cc = idx & 1023;
        float w;
        if (r < 64)       w = Wq[r*DMM + cc];
        else if (r < 128) w = Wk[(r-64)*DMM + cc];
        else if (r < 192) w = Wv[(r-128)*DMM + cc];
        else              w = Wa[(r-192)*DMM + cc];
        g_Wcat[idx] = w;
        if (bid == 64) {
            g_bcat[tid] = (tid < 64) ? bq[tid] :
                          (tid < 128) ? bk[tid-64] :
                          (tid < 192) ? bv[tid-128] : ba[tid-192];
        }
    } else if (bid < 3136) {
        int idx = (bid - 1088)*256 + tid;       // over 128*4096
        int c = idx >> 12, rest = idx & 4095;
        int j = rest >> 6, v = rest & 63;
        __nv_bfloat16 h, l;
        split_bf16(Wd[idx], h, l);
        size_t pos = (size_t)((c<<6) + v)*64 + j;
        g_Wd2h[pos] = h; g_Wd2l[pos] = l;
    } else {
        int idx = (bid - 3136)*256 + tid;       // over 4096*128
        int kv = idx >> 7, c = idx & 127;
        int k = kv >> 6, v = kv & 63;
        __nv_bfloat16 h, l;
        split_bf16(Wu[idx], h, l);
        size_t pos = (size_t)(v*128 + c)*64 + k;
        g_Wu3h[pos] = h; g_Wu3l[pos] = l;
    }
}

// ---------------- projection GEMM (K=1024), split/sigmoid/bf16 epilogue ----------------
__global__ void __launch_bounds__(256) gemm_proj(const float* __restrict__ A,
                                                 const float* __restrict__ B,
                                                 int M, int N, int K) {
    __shared__ __align__(16) float As[2][16][132];
    __shared__ __align__(16) float Bs[2][16][132];
    int tid = threadIdx.x;
    int tx = tid & 15, ty = tid >> 4;
    int row0 = blockIdx.y*128, col0 = blockIdx.x*128;
    int lr = tid >> 1;
    int lk = (tid & 1) * 8;
    const float* Ap = A + (size_t)(row0+lr)*K + lk;
    const float* Bp = B + (size_t)(col0+lr)*K + lk;

    unsigned long long acc[8][4];
    #pragma unroll
    for (int i = 0; i < 8; i++)
        #pragma unroll
        for (int j = 0; j < 4; j++) acc[i][j] = 0ULL;

    int nt = K >> 4;
    {
        float4 a0 = *(const float4*)(Ap + 0);
        float4 a1 = *(const float4*)(Ap + 4);
        float4 b0 = *(const float4*)(Bp + 0);
        float4 b1 = *(const float4*)(Bp + 4);
        As[0][lk+0][lr]=a0.x; As[0][lk+1][lr]=a0.y; As[0][lk+2][lr]=a0.z; As[0][lk+3][lr]=a0.w;
        As[0][lk+4][lr]=a1.x; As[0][lk+5][lr]=a1.y; As[0][lk+6][lr]=a1.z; As[0][lk+7][lr]=a1.w;
        Bs[0][lk+0][lr]=b0.x; Bs[0][lk+1][lr]=b0.y; Bs[0][lk+2][lr]=b0.z; Bs[0][lk+3][lr]=b0.w;
        Bs[0][lk+4][lr]=b1.x; Bs[0][lk+5][lr]=b1.y; Bs[0][lk+6][lr]=b1.z; Bs[0][lk+7][lr]=b1.w;
    }
    __syncthreads();

    #pragma unroll 1
    for (int t = 0; t < nt; t++) {
        int cur = t & 1;
        float4 a0, a1, b0, b1;
        if (t + 1 < nt) {
            int k0 = (t+1) << 4;
            a0 = *(const float4*)(Ap + k0);
            a1 = *(const float4*)(Ap + k0 + 4);
            b0 = *(const float4*)(Bp + k0);
            b1 = *(const float4*)(Bp + k0 + 4);
        }
        #pragma unroll
        for (int kk = 0; kk < 16; kk++) {
            float4 af0 = *(const float4*)&As[cur][kk][ty*8];
            float4 af1 = *(const float4*)&As[cur][kk][ty*8 + 4];
            ulonglong2 bv0 = *(const ulonglong2*)&Bs[cur][kk][tx*8];
            ulonglong2 bv1 = *(const ulonglong2*)&Bs[cur][kk][tx*8 + 4];
            float av[8] = {af0.x, af0.y, af0.z, af0.w, af1.x, af1.y, af1.z, af1.w};
            unsigned long long bw[4] = {bv0.x, bv0.y, bv1.x, bv1.y};
            #pragma unroll
            for (int i = 0; i < 8; i++) {
                unsigned long long ad = dupf(av[i]);
                #pragma unroll
                for (int j = 0; j < 4; j++) fma2(acc[i][j], ad, bw[j]);
            }
        }
        if (t + 1 < nt) {
            int nb = cur ^ 1;
            As[nb][lk+0][lr]=a0.x; As[nb][lk+1][lr]=a0.y; As[nb][lk+2][lr]=a0.z; As[nb][lk+3][lr]=a0.w;
            As[nb][lk+4][lr]=a1.x; As[nb][lk+5][lr]=a1.y; As[nb][lk+6][lr]=a1.z; As[nb][lk+7][lr]=a1.w;
            Bs[nb][lk+0][lr]=b0.x; Bs[nb][lk+1][lr]=b0.y; Bs[nb][lk+2][lr]=b0.z; Bs[nb][lk+3][lr]=b0.w;
            Bs[nb][lk+4][lr]=b1.x; Bs[nb][lk+5][lr]=b1.y; Bs[nb][lk+6][lr]=b1.z; Bs[nb][lk+7][lr]=b1.w;
        }
        __syncthreads();
    }

    #pragma unroll
    for (int i = 0; i < 8; i++) {
        int m = row0 + ty*8 + i;
        float val[8];
        unpk(acc[i][0], val[0], val[1]); unpk(acc[i][1], val[2], val[3]);
        unpk(acc[i][2], val[4], val[5]); unpk(acc[i][3], val[6], val[7]);
        int n0 = col0 + tx*8;
        const float* bp = g_bcat + n0;
        #pragma unroll
        for (int e = 0; e < 8; e++) val[e] += bp[e];
        int blk = n0 >> 6;
        int w = n0 & 63;
        if (blk == 2) {
            *(float4*)(g_v + (size_t)m*64 + w)     = *(float4*)&val[0];
            *(float4*)(g_v + (size_t)m*64 + w + 4) = *(float4*)&val[4];
        } else {
            __nv_bfloat16* bh;
            __nv_bfloat16* bl;
            if (blk == 0)      { bh = g_qh; bl = g_ql; }
            else if (blk == 1) { bh = g_kh; bl = g_kl; }
            else               { bh = g_ah; bl = g_al;
                #pragma unroll
                for (int e = 0; e < 8; e++) val[e] = 1.f/(1.f+expf(-val[e]));
            }
            __nv_bfloat16 h8[8], l8[8];
            #pragma unroll
            for (int e = 0; e < 8; e++) split_bf16(val[e], h8[e], l8[e]);
            *(uint4*)(bh + (size_t)m*64 + w) = *(uint4*)h8;
            *(uint4*)(bl + (size_t)m*64 + w) = *(uint4*)l8;
        }
    }
}

// ---------------- mma.sync bf16-split K=64 GEMM, 128x128 tile, 256 threads ----------------
// MODE 0: split D -> g_Ah/g_Al (bf16 pair), smem-staged coalesced store.
// MODE 1: bin epilogue. MODE 2: o epilogue.
#define TILEB 18432              /* 128 rows * 144 B */
#define EPI_OFF (4*TILEB)        /* 73728 */
template<int MODE>
__global__ void __launch_bounds__(256) hgemm(const __nv_bfloat16* __restrict__ Ah,
                                             const __nv_bfloat16* __restrict__ Al,
                                             const __nv_bfloat16* __restrict__ Bh,
                                             const __nv_bfloat16* __restrict__ Bl,
                                             float* __restrict__ C) {
    extern __shared__ __align__(16) char smem[];
    uint32_t sb = smem_u32(smem);
    int tid = threadIdx.x;
    int lane = tid & 31, wid = tid >> 5;
    int gid = lane >> 2, tig = lane & 3;
    int warpM = wid >> 2, warpN = wid & 3;
    int m0 = warpM*64, n0 = warpN*32;
    int row0 = blockIdx.y*128, col0 = blockIdx.x*128;

    {
        const uint4* srcs[4] = {
            (const uint4*)(Ah + (size_t)row0*64), (const uint4*)(Al + (size_t)row0*64),
            (const uint4*)(Bh + (size_t)col0*64), (const uint4*)(Bl + (size_t)col0*64) };
        #pragma unroll
        for (int t = 0; t < 4; t++) {
            char* dst = smem + t*TILEB;
            #pragma unroll
            for (int j = 0; j < 4; j++) {
                int idx = tid + j*256;
                int r = idx >> 3, ch = idx & 7;
                *(uint4*)(dst + r*144 + ch*16) = srcs[t][idx];
            }
        }
    }
    if (MODE == 1) {
        float* sv = (float*)(smem + EPI_OFF);
        const float4* vp = (const float4*)(g_v + (size_t)row0*64);
        #pragma unroll
        for (int j = 0; j < 8; j++) {
            int idx = tid + j*256;
            int r = idx >> 4, q = idx & 15;
            *(float4*)&sv[r*68 + q*4] = vp[idx];
        }
    }
    if (MODE == 2) {
        float* sc = (float*)(smem + EPI_OFF);
        const float4* cp = (const float4*)(g_c + (size_t)row0*128);
        #pragma unroll
        for (int j = 0; j < 16; j++) {
            int idx = tid + j*256;
            int r = idx >> 5, q = idx & 31;
            *(float4*)&sc[r*132 + q*4] = cp[idx];
        }
    }
    __syncthreads();

    int q8 = lane >> 3, i8 = lane & 7;
    uint32_t aLane = (uint32_t)(((q8 & 1)*8 + i8)*144 + (q8 >> 1)*16);
    uint32_t bLane = (uint32_t)(((q8 >> 1)*8 + i8)*144 + (q8 & 1)*16);

    float d[4][4][4];
    #pragma unroll
    for (int mt = 0; mt < 4; mt++)
        #pragma unroll
        for (int nt = 0; nt < 4; nt++)
            #pragma unroll
            for (int e = 0; e < 4; e++) d[mt][nt][e] = 0.f;

    #pragma unroll
    for (int term = 0; term < 3; term++) {
        uint32_t aBase = sb + (term == 2 ? TILEB : 0) + (uint32_t)m0*144 + aLane;
        uint32_t bBase = sb + 2*TILEB + (term == 1 ? TILEB : 0) + (uint32_t)n0*144 + bLane;
        #pragma unroll
        for (int ks = 0; ks < 4; ks++) {
            uint32_t koff = (uint32_t)(ks*32);
            uint32_t af[4][4], bf2[2][4];
            #pragma unroll
            for (int mt = 0; mt < 4; mt++)
                LDSM4(af[mt], aBase + mt*16*144 + koff);
            #pragma unroll
            for (int nt2 = 0; nt2 < 2; nt2++)
                LDSM4(bf2[nt2], bBase + nt2*16*144 + koff);
            #pragma unroll
            for (int mt = 0; mt < 4; mt++)
                #pragma unroll
                for (int nt = 0; nt < 4; nt++)
                    MMA16816(d[mt][nt], af[mt], bf2[nt>>1][(nt&1)*2], bf2[nt>>1][(nt&1)*2+1]);
        }
    }
    __syncthreads();

    if (MODE == 0) {
        __nv_bfloat16* Dh = (__nv_bfloat16*)smem;              // [128][136]
        __nv_bfloat16* Dl = (__nv_bfloat16*)(smem + 34816);
        #pragma unroll
        for (int mt = 0; mt < 4; mt++) {
            int r0 = m0 + mt*16 + gid, r1 = r0 + 8;
            #pragma unroll
            for (int nt = 0; nt < 4; nt++) {
                int cl = n0 + nt*8 + tig*2;
                __nv_bfloat16 h2[2], l2[2];
                split_bf16(d[mt][nt][0], h2[0], l2[0]);
                split_bf16(d[mt][nt][1], h2[1], l2[1]);
                *(uint32_t*)&Dh[r0*136 + cl] = *(uint32_t*)h2;
                *(uint32_t*)&Dl[r0*136 + cl] = *(uint32_t*)l2;
                split_bf16(d[mt][nt][2], h2[0], l2[0]);
                split_bf16(d[mt][nt][3], h2[1], l2[1]);
                *(uint32_t*)&Dh[r1*136 + cl] = *(uint32_t*)h2;
                *(uint32_t*)&Dl[r1*136 + cl] = *(uint32_t*)l2;
            }
        }
        __syncthreads();
        #pragma unroll
        for (int it = 0; it < 8; it++) {
            int idx = tid + it*256;              // 2048 16B chunks each
            int r = idx >> 4, ch = idx & 15;
            *(uint4*)(g_Ah + (size_t)(row0+r)*16384 + col0 + ch*8) =
                *(const uint4*)((const char*)Dh + r*272 + ch*16);
            *(uint4*)(g_Al + (size_t)(row0+r)*16384 + col0 + ch*8) =
                *(const uint4*)((const char*)Dl + r*272 + ch*16);
        }
    } else if (MODE == 1) {
        const float* sv = (const float*)(smem + EPI_OFF);
        float* red = (float*)smem;
        #pragma unroll
        for (int mt = 0; mt < 4; mt++) {
            int r0 = m0 + mt*16 + gid, r1 = r0 + 8;
            float p0 = 0.f, p1 = 0.f;
            #pragma unroll
            for (int nt = 0; nt < 4; nt++) {
                int v = (n0 + nt*8 + tig*2) & 63;
                p0 += d[mt][nt][0]*sv[r0*68 + v] + d[mt][nt][1]*sv[r0*68 + v + 1];
                p1 += d[mt][nt][2]*sv[r1*68 + v] + d[mt][nt][3]*sv[r1*68 + v + 1];
            }
            p0 += __shfl_xor_sync(0xffffffffu, p0, 1);
            p0 += __shfl_xor_sync(0xffffffffu, p0, 2);
            p1 += __shfl_xor_sync(0xffffffffu, p1, 1);
            p1 += __shfl_xor_sync(0xffffffffu, p1, 2);
            if (tig == 0) { red[r0*4 + warpN] = p0; red[r1*4 + warpN] = p1; }
        }
        __syncthreads();
        if (tid < 128) {
            int cb = blockIdx.x*2;
            float s0 = red[tid*4 + 0] + red[tid*4 + 1];
            float s1 = red[tid*4 + 2] + red[tid*4 + 3];
            g_bin[(size_t)(row0 + tid)*128 + cb]     = s0;
            g_bin[(size_t)(row0 + tid)*128 + cb + 1] = s1;
        }
    } else {
        const float* sc = (const float*)(smem + EPI_OFF);
        float* red = (float*)smem;
        #pragma unroll
        for (int mt = 0; mt < 4; mt++) {
            int r0 = m0 + mt*16 + gid, r1 = r0 + 8;
            float p0 = 0.f, p1 = 0.f;
            #pragma unroll
            for (int nt = 0; nt < 4; nt++) {
                int c = n0 + nt*8 + tig*2;
                p0 += d[mt][nt][0]*sc[r0*132 + c] + d[mt][nt][1]*sc[r0*132 + c + 1];
                p1 += d[mt][nt][2]*sc[r1*132 + c] + d[mt][nt][3]*sc[r1*132 + c + 1];
            }
            p0 += __shfl_xor_sync(0xffffffffu, p0, 1);
            p0 += __shfl_xor_sync(0xffffffffu, p0, 2);
            p1 += __shfl_xor_sync(0xffffffffu, p1, 1);
            p1 += __shfl_xor_sync(0xffffffffu, p1, 2);
            if (tig == 0) { red[r0*4 + warpN] = p0; red[r1*4 + warpN] = p1; }
        }
        __syncthreads();
        if (tid < 128) {
            float s = red[tid*4+0] + red[tid*4+1] + red[tid*4+2] + red[tid*4+3];
            C[(size_t)(row0 + tid)*64 + blockIdx.x] = s;
        }
    }
}

// ---------------- pass A (mma.sync, bf16 A staged directly via cp.async) ----------------
#define PA_QH  0         /* bf16 [128][136] = 34816 */
#define PA_QL  34816
#define PA_AB  69632     /* A buffers: buf b -> h at PA_AB + b*69632, l at +34816 */
#define PA_BUFS 69632
#define PA_DS  208896    /* fp32 [2][128] */
#define PA_SMEM 209920
__global__ __launch_bounds__(512) void passA_mma() {
    extern __shared__ __align__(16) char sm[];
    uint32_t sb = smem_u32(sm);
    __nv_bfloat16* sQh = (__nv_bfloat16*)(sm + PA_QH);
    __nv_bfloat16* sQl = (__nv_bfloat16*)(sm + PA_QL);
    float* ds = (float*)(sm + PA_DS);

    int tid = threadIdx.x;
    int lane = tid & 31, wid = tid >> 5;
    int gid = lane >> 2, tig = lane & 3;
    int wm = wid >> 2, wn = wid & 3;
    int chunk = blockIdx.x;
    int b = chunk >> 5, ci = chunk & 31;
    size_t tokBase = (size_t)b*SS + (size_t)ci*CHL;

    for (int idx = tid; idx < 128*136; idx += 512) {
        int r = idx / 136, k = idx - r*136;
        sQh[idx] = __float2bfloat16(r == k ? 1.f : 0.f);
        sQl[idx] = __float2bfloat16(0.f);
    }
    if (tid < 256) ds[tid] = 0.f;

    // prologue: stage A(0) into buf0 with plain ld/st (hardened)
    {
        const uint4* Hh = (const uint4*)(g_Ah + tokBase*16384);
        const uint4* Hl = (const uint4*)(g_Al + tokBase*16384);
        #pragma unroll
        for (int j = 0; j < 4; j++) {
            int idx = tid + j*512;
            int r = idx >> 4, ch = idx & 15;
            *(uint4*)(sm + PA_AB + r*272 + ch*16) = Hh[idx];
            *(uint4*)(sm + PA_AB + 34816 + r*272 + ch*16) = Hl[idx];
        }
    }
    __syncthreads();

    int q8 = lane >> 3, i8 = lane & 7;
    uint32_t aLane = (uint32_t)(((q8 & 1)*8 + i8)*272 + (q8 >> 1)*16);
    uint32_t bLane = (uint32_t)(((q8 >> 1)*8 + i8)*272 + (q8 & 1)*16);
    uint32_t qhB = sb + PA_QH + (uint32_t)(wm*32)*272 + aLane;
    uint32_t qlB = sb + PA_QL + (uint32_t)(wm*32)*272 + aLane;

    int drw = tid >> 2, dq = tid & 3;
    int cur = 0;
    for (int s = 0; s < CHL; s++) {
        // 1. prefetch next A into buf cur^1
        if (s + 1 < CHL) {
            const __nv_bfloat16* Hh = g_Ah + (tokBase + s + 1)*16384;
            const __nv_bfloat16* Hl = g_Al + (tokBase + s + 1)*16384;
            uint32_t db = sb + PA_AB + (uint32_t)(cur^1)*PA_BUFS;
            #pragma unroll
            for (int j = 0; j < 4; j++) {
                int idx = tid + j*512;
                int r = idx >> 4, ch = idx & 15;
                CP16(db + r*272 + ch*16, Hh + idx*8);
                CP16(db + 34816 + r*272 + ch*16, Hl + idx*8);
            }
            CP_COMMIT();
        }
        // 2. fp32 d-update from buf cur (h+l reconstruct)
        {
            const __nv_bfloat16* ah = (const __nv_bfloat16*)(sm + PA_AB + (size_t)cur*PA_BUFS);
            const __nv_bfloat16* al = ah + 17408;   // +34816 bytes
            const float* dc = ds + cur*128;
            float dacc = 0.f;
            #pragma unroll
            for (int kk = 0; kk < 32; kk++) {
                int k = dq*32 + ((kk + lane) & 31);
                float av = __bfloat162float(ah[drw*136 + k]) + __bfloat162float(al[drw*136 + k]);
                dacc += av * dc[k];
            }
            dacc += __shfl_xor_sync(0xffffffffu, dacc, 1);
            dacc += __shfl_xor_sync(0xffffffffu, dacc, 2);
            if (dq == 0)
                ds[(cur^1)*128 + drw] = dacc + g_bin[(tokBase + s)*128 + drw];
        }
        // 3. newQ = Q @ A^T, 3-term bf16-split
        uint32_t abse = sb + PA_AB + (uint32_t)cur*PA_BUFS;
        uint32_t ahB = abse + (uint32_t)(wn*32)*272 + bLane;
        uint32_t alB = abse + 34816 + (uint32_t)(wn*32)*272 + bLane;
        float acc[2][4][4];
        #pragma unroll
        for (int mt = 0; mt < 2; mt++)
            #pragma unroll
            for (int nt = 0; nt < 4; nt++)
                #pragma unroll
                for (int e = 0; e < 4; e++) acc[mt][nt][e] = 0.f;
        #pragma unroll
        for (int ks = 0; ks < 8; ks++) {
            uint32_t ko = (uint32_t)(ks*32);
            uint32_t qh[2][4], ql[2][4], ah[2][4], al[2][4];
            #pragma unroll
            for (int mt = 0; mt < 2; mt++) {
                LDSM4(qh[mt], qhB + mt*16*272 + ko);
                LDSM4(ql[mt], qlB + mt*16*272 + ko);
            }
            #pragma unroll
            for (int nb = 0; nb < 2; nb++) {
                LDSM4(ah[nb], ahB + nb*16*272 + ko);
                LDSM4(al[nb], alB + nb*16*272 + ko);
            }
            #pragma unroll
            for (int mt = 0; mt < 2; mt++)
                #pragma unroll
                for (int nt = 0; nt < 4; nt++) {
                    int nb = nt >> 1, hh = (nt & 1)*2;
                    MMA16816(acc[mt][nt], qh[mt], ah[nb][hh], ah[nb][hh+1]);
                    MMA16816(acc[mt][nt], qh[mt], al[nb][hh], al[nb][hh+1]);
                    MMA16816(acc[mt][nt], ql[mt], ah[nb][hh], ah[nb][hh+1]);
                }
        }
        __syncthreads();   // Q reads + d reads complete
        // 4. writeback newQ (bf16 split) or final fp32 to g_P
        if (s + 1 < CHL) {
            #pragma unroll
            for (int mt = 0; mt < 2; mt++)
                #pragma unroll
                for (int nt = 0; nt < 4; nt++) {
                    int r0 = wm*32 + mt*16 + gid, r1 = r0 + 8;
                    int col = wn*32 + nt*8 + tig*2;
                    __nv_bfloat16 hp[2], lp[2];
                    split_bf16(acc[mt][nt][0], hp[0], lp[0]);
                    split_bf16(acc[mt][nt][1], hp[1], lp[1]);
                    *(uint32_t*)&sQh[r0*136 + col] = *(uint32_t*)hp;
                    *(uint32_t*)&sQl[r0*136 + col] = *(uint32_t*)lp;
                    split_bf16(acc[mt][nt][2], hp[0], lp[0]);
                    split_bf16(acc[mt][nt][3], hp[1], lp[1]);
                    *(uint32_t*)&sQh[r1*136 + col] = *(uint32_t*)hp;
                    *(uint32_t*)&sQl[r1*136 + col] = *(uint32_t*)lp;
                }
        } else {
            float* Pout = g_P + (size_t)chunk*16384;
            #pragma unroll
            for (int mt = 0; mt < 2; mt++)
                #pragma unroll
                for (int nt = 0; nt < 4; nt++) {
                    int r0 = wm*32 + mt*16 + gid, r1 = r0 + 8;
                    int col = wn*32 + nt*8 + tig*2;
                    *(float2*)&Pout[r0*128 + col] = make_float2(acc[mt][nt][0], acc[mt][nt][1]);
                    *(float2*)&Pout[r1*128 + col] = make_float2(acc[mt][nt][2], acc[mt][nt][3]);
                }
        }
        CP_WAIT0();        // hardened: unconditional drain of any outstanding cp.async
        __syncthreads();
        cur ^= 1;
    }
    if (tid < 128) g_d[chunk*128 + tid] = ds[cur*128 + tid];
}

// ---------------- pass B: cross-chunk scan (reads Q = P^T layout) ----------------
__global__ __launch_bounds__(512) void passB_kern() {
    int b = blockIdx.x;
    int tid = threadIdx.x;
    __shared__ float cv[128], nv[128], red[512];
    if (tid < 128) cv[tid] = 0.f;
    __syncthreads();
    int g = tid >> 7, r = tid & 127;
    for (int i = 0; i < SS/CHL; i++) {
        int chunk = b*(SS/CHL) + i;
        if (tid < 128) g_cb[chunk*128 + tid] = cv[tid];
        __syncthreads();
        const float* Q = g_P + (size_t)chunk*16384;
        float acc = 0.f;
        #pragma unroll 8
        for (int kk = 0; kk < 32; kk++) {
            int k = g*32 + kk;
            acc += Q[k*128 + r] * cv[k];     // P[r][k] = Q[k][r]
        }
        red[g*128 + r] = acc;
        __syncthreads();
        if (tid < 128)
            nv[tid] = red[tid] + red[128+tid] + red[256+tid] + red[384+tid]
                    + g_d[chunk*128 + tid];
        __syncthreads();
        if (tid < 128) cv[tid] = nv[tid];
        __syncthreads();
    }
}

// ---------------- pass C: within-chunk recurrence (bf16 h+l A) ----------------
__global__ __launch_bounds__(512) void passC_kern() {
    int chunk = blockIdx.x;
    int b = chunk >> 5, ci = chunk & 31;
    size_t tokBase = (size_t)b*SS + (size_t)ci*CHL;
    int tid = threadIdx.x;
    int r = tid >> 2, dq = tid & 3;
    __shared__ float cs[2][128];
    if (tid < 128) cs[0][tid] = g_cb[chunk*128 + tid];
    __syncthreads();

    const uint4* Hh = (const uint4*)(g_Ah + tokBase*16384);
    const uint4* Hl = (const uint4*)(g_Al + tokBase*16384);
    int base = r*16 + dq*4;
    uint4 bh[4], bl[4];
    #pragma unroll
    for (int j = 0; j < 4; j++) {
        int pj = (j + dq) & 3;
        bh[j] = Hh[base + pj];
        bl[j] = Hl[base + pj];
    }

    int p = 0;
    for (int s = 0; s < CHL; s++) {
        uint4 nh[4], nl[4];
        if (s + 1 < CHL) {
            const uint4* H2 = Hh + (size_t)(s+1)*2048;
            const uint4* L2 = Hl + (size_t)(s+1)*2048;
            #pragma unroll
            for (int j = 0; j < 4; j++) {
                int pj = (j + dq) & 3;
                nh[j] = H2[base + pj];
                nl[j] = L2[base + pj];
            }
        }
        float acc = 0.f;
        #pragma unroll
        for (int j = 0; j < 4; j++) {
            int pj = (j + dq) & 3;
            const __nv_bfloat162* hp = (const __nv_bfloat162*)&bh[j];
            const __nv_bfloat162* lp = (const __nv_bfloat162*)&bl[j];
            float4 cv0 = *(const float4*)&cs[p][dq*32 + pj*8];
            float4 cv1 = *(const float4*)&cs[p][dq*32 + pj*8 + 4];
            float2 h0 = __bfloat1622float2(hp[0]), l0 = __bfloat1622float2(lp[0]);
            float2 h1 = __bfloat1622float2(hp[1]), l1 = __bfloat1622float2(lp[1]);
            float2 h2 = __bfloat1622float2(hp[2]), l2 = __bfloat1622float2(lp[2]);
            float2 h3 = __bfloat1622float2(hp[3]), l3 = __bfloat1622float2(lp[3]);
            acc += (h0.x+l0.x)*cv0.x + (h0.y+l0.y)*cv0.y
                 + (h1.x+l1.x)*cv0.z + (h1.y+l1.y)*cv0.w
                 + (h2.x+l2.x)*cv1.x + (h2.y+l2.y)*cv1.y
                 + (h3.x+l3.x)*cv1.z + (h3.y+l3.y)*cv1.w;
        }
        acc += __shfl_xor_sync(0xffffffffu, acc, 1);
        acc += __shfl_xor_sync(0xffffffffu, acc, 2);
        if (dq == 0) {
            float cn = acc + g_bin[(tokBase + s)*128 + r];
            cs[p ^ 1][r] = cn;
            g_c[(tokBase + s)*128 + r] = cn;
        }
        __syncthreads();
        p ^= 1;
        #pragma unroll
        for (int j = 0; j < 4; j++) { bh[j] = nh[j]; bl[j] = nl[j]; }
    }
}

// ---------------- host launcher ----------------
extern "C" void kernel_launch(void* const* d_in, const int* in_sizes, int n_in,
                              void* d_out, int out_size) {
    const float* x   = (const float*)d_in[0];
    const float* Wq  = (const float*)d_in[1];
    const float* bq  = (const float*)d_in[2];
    const float* Wk  = (const float*)d_in[3];
    const float* bk  = (const float*)d_in[4];
    const float* Wv  = (const float*)d_in[5];
    const float* bv  = (const float*)d_in[6];
    const float* Wa  = (const float*)d_in[7];
    const float* ba  = (const float*)d_in[8];
    const float* Wdn = (const float*)d_in[9];
    const float* Wup = (const float*)d_in[10];
    float* out = (float*)d_out;

    float *pWcat;
    __nv_bfloat16 *pQh, *pQl, *pKh, *pKl, *pAh, *pAl, *pMTh, *pMTl, *pWd2h, *pWd2l, *pWu3h, *pWu3l;
    cudaGetSymbolAddress((void**)&pWcat, g_Wcat);
    cudaGetSymbolAddress((void**)&pQh,   g_qh);
    cudaGetSymbolAddress((void**)&pQl,   g_ql);
    cudaGetSymbolAddress((void**)&pKh,   g_kh);
    cudaGetSymbolAddress((void**)&pKl,   g_kl);
    cudaGetSymbolAddress((void**)&pAh,   g_ah);
    cudaGetSymbolAddress((void**)&pAl,   g_al);
    cudaGetSymbolAddress((void**)&pMTh,  g_MTh);
    cudaGetSymbolAddress((void**)&pMTl,  g_MTl);
    cudaGetSymbolAddress((void**)&pWd2h, g_Wd2h);
    cudaGetSymbolAddress((void**)&pWd2l, g_Wd2l);
    cudaGetSymbolAddress((void**)&pWu3h, g_Wu3h);
    cudaGetSymbolAddress((void**)&pWu3l, g_Wu3l);

    cudaFuncSetAttribute(passA_mma, cudaFuncAttributeMaxDynamicSharedMemorySize, PA_SMEM);

    const int SM0 = EPI_OFF;                 // 73728
    const int SM1 = EPI_OFF + 128*68*4;      // 108544
    const int SM2 = EPI_OFF + 128*132*4;     // 141312
    cudaFuncSetAttribute(hgemm<0>, cudaFuncAttributeMaxDynamicSharedMemorySize, SM0);
    cudaFuncSetAttribute(hgemm<1>, cudaFuncAttributeMaxDynamicSharedMemorySize, SM1);
    cudaFuncSetAttribute(hgemm<2>, cudaFuncAttributeMaxDynamicSharedMemorySize, SM2);

    // 1. weight prep (bf16 splits)
    prep_all<<<5184, 256>>>(Wq, bq, Wk, bk, Wv, bv, Wa, ba, Wdn, Wup);
    // 2. projection + split/sigmoid/bf16 epilogue
    gemm_proj<<<dim3(2, 64), 256>>>(x, pWcat, NTOK, 256, DMM);
    // 3. bin mma-GEMM (k @ Wd2^T, fused v-contraction -> g_bin)
    hgemm<1><<<dim3(64, 64), 256, SM1>>>(pKh, pKl, pWd2h, pWd2l, nullptr);
    // 4. A mma-GEMM (alpha @ MT^T -> g_Ah/g_Al bf16 split)   <-- ncu capture slot
    hgemm<0><<<dim3(128, 64), 256, SM0>>>(pAh, pAl, pMTh, pMTl, nullptr);
    // 5. chunk propagators (tensor cores, direct bf16 staging)
    passA_mma<<<NCH, 512, PA_SMEM>>>();
    // 6. cross-chunk scan
    passB_kern<<<BB, 512>>>();
    // 7. within-chunk recurrence (bf16 h+l A)
    passC_kern<<<NCH, 512>>>();
    // 8. o mma-GEMM (q @ Wu3^T, fused c-contraction -> out)
    hgemm<2><<<dim3(64, 64), 256, SM2>>>(pQh, pQl, pWu3h, pWu3l, out);
}